// round 1
// baseline (speedup 1.0000x reference)
#include <cuda_runtime.h>
#include <cuda_bf16.h>
#include <mma.h>

using namespace nvcuda;

// Problem shape (fixed): B=4, S=1024, D=4096, H=32, HD=128
#define NB 4
#define NS 1024
#define ND 4096
#define NH 32
#define NHD 128
#define NTOK (NB * NS)          // 4096 rows

// Scratch (device globals: the sanctioned no-alloc workaround). 4 x 64MB.
__device__ float g_q[(size_t)NTOK * ND];
__device__ float g_k[(size_t)NTOK * ND];
__device__ float g_v[(size_t)NTOK * ND];
__device__ float g_attn[(size_t)NTOK * ND];

// ---------------------------------------------------------------------------
// GEMM: C[m,n] = sum_k A[m,k] * W[n,k]   (A: [4096,4096] rm, W: [4096,4096] rm)
// tf32 wmma m16n16k8. Block tile 128x128x32, 256 threads = 8 warps (2x4),
// each warp 64x32 = 4x2 fragments.
// mode 0: A = A_ext, C = {g_q, g_k, g_v}[blockIdx.z], W = {W0,W1,W2}
// mode 1: A = g_attn, C = C_ext, W = W0
// ---------------------------------------------------------------------------
__global__ __launch_bounds__(256) void gemm_tf32_kernel(
    const float* __restrict__ A_ext,
    const float* __restrict__ W0, const float* __restrict__ W1,
    const float* __restrict__ W2,
    float* __restrict__ C_ext, int mode)
{
    constexpr int LD = 40;  // 32 + 8 pad: keeps fragment ptrs 32B aligned
    __shared__ float As[128 * LD];
    __shared__ float Bs[128 * LD];

    const int z = blockIdx.z;
    const float* W = (z == 0) ? W0 : (z == 1) ? W1 : W2;
    const float* A;
    float* C;
    if (mode == 0) {
        A = A_ext;
        C = (z == 0) ? g_q : (z == 1) ? g_k : g_v;
    } else {
        A = g_attn;
        C = C_ext;
    }

    const int tid = threadIdx.x;
    const int m0 = blockIdx.y * 128;
    const int n0 = blockIdx.x * 128;
    const int warp = tid >> 5;
    const int wm = warp >> 2;   // 0..1
    const int wn = warp & 3;    // 0..3

    wmma::fragment<wmma::accumulator, 16, 16, 8, float> acc[4][2];
#pragma unroll
    for (int i = 0; i < 4; i++)
#pragma unroll
        for (int j = 0; j < 2; j++)
            wmma::fill_fragment(acc[i][j], 0.0f);

    for (int k0 = 0; k0 < ND; k0 += 32) {
#pragma unroll
        for (int t = 0; t < 4; t++) {
            int e = tid + t * 256;          // 0..1023
            int r = e >> 3;
            int c4 = (e & 7) << 2;
            *(float4*)&As[r * LD + c4] =
                *(const float4*)&A[(size_t)(m0 + r) * ND + k0 + c4];
            *(float4*)&Bs[r * LD + c4] =
                *(const float4*)&W[(size_t)(n0 + r) * ND + k0 + c4];
        }
        __syncthreads();
#pragma unroll
        for (int kk = 0; kk < 32; kk += 8) {
            wmma::fragment<wmma::matrix_a, 16, 16, 8, wmma::precision::tf32,
                           wmma::row_major> af[4];
            wmma::fragment<wmma::matrix_b, 16, 16, 8, wmma::precision::tf32,
                           wmma::col_major> bf[2];
#pragma unroll
            for (int i = 0; i < 4; i++) {
                wmma::load_matrix_sync(af[i], &As[(wm * 64 + i * 16) * LD + kk], LD);
#pragma unroll
                for (int t = 0; t < af[i].num_elements; t++)
                    af[i].x[t] = wmma::__float_to_tf32(af[i].x[t]);
            }
#pragma unroll
            for (int j = 0; j < 2; j++) {
                wmma::load_matrix_sync(bf[j], &Bs[(wn * 32 + j * 16) * LD + kk], LD);
#pragma unroll
                for (int t = 0; t < bf[j].num_elements; t++)
                    bf[j].x[t] = wmma::__float_to_tf32(bf[j].x[t]);
            }
#pragma unroll
            for (int i = 0; i < 4; i++)
#pragma unroll
                for (int j = 0; j < 2; j++)
                    wmma::mma_sync(acc[i][j], af[i], bf[j], acc[i][j]);
        }
        __syncthreads();
    }

#pragma unroll
    for (int i = 0; i < 4; i++)
#pragma unroll
        for (int j = 0; j < 2; j++)
            wmma::store_matrix_sync(
                &C[(size_t)(m0 + wm * 64 + i * 16) * ND + n0 + wn * 32 + j * 16],
                acc[i][j], ND, wmma::mem_row_major);
}

// ---------------------------------------------------------------------------
// RoPE, in-place on g_q and g_k. One thread per (re,im) pair.
// Layout: row = b*S+s (4096 rows), col = h*128 + d; pair index within head = d/2.
// total pairs = 2 tensors * 4096 * 2048 = 16,777,216 = 65536 blocks * 256.
// ---------------------------------------------------------------------------
__global__ void rope_kernel(const float* __restrict__ fcos,
                            const float* __restrict__ fsin)
{
    int gid = blockIdx.x * blockDim.x + threadIdx.x;
    float* t = (gid < (1 << 23)) ? g_q : g_k;
    int p = gid & ((1 << 23) - 1);
    int row = p >> 11;           // 2048 pairs per row
    int pair = p & 2047;
    int i = pair & 63;           // pair index within head (HD/2 = 64)
    int s = row & 1023;          // sequence position
    float c = fcos[s * 64 + i];
    float sn = fsin[s * 64 + i];
    float2 v = *(float2*)&t[(size_t)row * ND + pair * 2];
    float2 o;
    o.x = v.x * c - v.y * sn;
    o.y = v.x * sn + v.y * c;
    *(float2*)&t[(size_t)row * ND + pair * 2] = o;
}

// ---------------------------------------------------------------------------
// Flash attention (online softmax), causal. Grid: (S/64, H, B). 256 threads
// as 16x16: thread (ty,tx) owns score rows ty*4..+4, score cols tx+16j (j<4),
// and O cols tx*8..+8. Tiles of 64 keys. Dynamic smem = 113 KB.
// ---------------------------------------------------------------------------
__global__ __launch_bounds__(256, 2) void attn_kernel()
{
    extern __shared__ float sm[];
    float* Qs = sm;                   // 64*128
    float* Ks = Qs + 64 * 128;        // 64*132 (pad 4 vs strided col reads)
    float* Vs = Ks + 64 * 132;        // 64*128
    float* Ps = Vs + 64 * 128;        // 64*64

    const int tid = threadIdx.x;
    const int ty = tid >> 4;
    const int tx = tid & 15;
    const int qt = blockIdx.x;
    const int h = blockIdx.y;
    const int b = blockIdx.z;
    const int q0 = qt * 64;

    const float scale = 0.08838834764831845f;  // 1/sqrt(128)
    const size_t base = (size_t)b * NS * ND + (size_t)h * NHD;

    // Load Q tile, pre-scaled
#pragma unroll
    for (int t = 0; t < 8; t++) {
        int e = tid + t * 256;
        int r = e >> 5;
        int c4 = (e & 31) << 2;
        float4 v = *(const float4*)&g_q[base + (size_t)(q0 + r) * ND + c4];
        v.x *= scale; v.y *= scale; v.z *= scale; v.w *= scale;
        *(float4*)&Qs[r * 128 + c4] = v;
    }

    float m_st[4], l_st[4], oacc[4][8];
#pragma unroll
    for (int i = 0; i < 4; i++) {
        m_st[i] = -1e30f;
        l_st[i] = 0.f;
#pragma unroll
        for (int c = 0; c < 8; c++) oacc[i][c] = 0.f;
    }

    for (int jt = 0; jt <= qt; jt++) {
        __syncthreads();  // protects Qs(first iter) & Ks/Vs/Ps from prior readers
#pragma unroll
        for (int t = 0; t < 8; t++) {
            int e = tid + t * 256;
            int r = e >> 5;
            int c4 = (e & 31) << 2;
            size_t g = base + (size_t)(jt * 64 + r) * ND + c4;
            *(float4*)&Ks[r * 132 + c4] = *(const float4*)&g_k[g];
            *(float4*)&Vs[r * 128 + c4] = *(const float4*)&g_v[g];
        }
        __syncthreads();

        // S = Qs * Ks^T   (4x4 per thread)
        float s[4][4];
#pragma unroll
        for (int i = 0; i < 4; i++)
#pragma unroll
            for (int j = 0; j < 4; j++) s[i][j] = 0.f;

        for (int d = 0; d < 128; d += 4) {
            float4 qv[4], kv[4];
#pragma unroll
            for (int i = 0; i < 4; i++)
                qv[i] = *(float4*)&Qs[(ty * 4 + i) * 128 + d];
#pragma unroll
            for (int j = 0; j < 4; j++)
                kv[j] = *(float4*)&Ks[(tx + 16 * j) * 132 + d];
#pragma unroll
            for (int i = 0; i < 4; i++)
#pragma unroll
                for (int j = 0; j < 4; j++)
                    s[i][j] += qv[i].x * kv[j].x + qv[i].y * kv[j].y +
                               qv[i].z * kv[j].z + qv[i].w * kv[j].w;
        }

        // Causal mask: only the diagonal tile needs elementwise masking
        if (jt == qt) {
#pragma unroll
            for (int i = 0; i < 4; i++)
#pragma unroll
                for (int j = 0; j < 4; j++)
                    if (tx + 16 * j > ty * 4 + i) s[i][j] = -1e30f;
        }

        // Online softmax (row reduce over tx = 16 lanes within each warp half)
#pragma unroll
        for (int i = 0; i < 4; i++) {
            float mx = fmaxf(fmaxf(s[i][0], s[i][1]), fmaxf(s[i][2], s[i][3]));
#pragma unroll
            for (int o = 8; o >= 1; o >>= 1)
                mx = fmaxf(mx, __shfl_xor_sync(0xffffffffu, mx, o));
            float mnew = fmaxf(m_st[i], mx);
            float alpha = __expf(m_st[i] - mnew);
            float rsum = 0.f;
#pragma unroll
            for (int j = 0; j < 4; j++) {
                float p = __expf(s[i][j] - mnew);
                Ps[(ty * 4 + i) * 64 + tx + 16 * j] = p;
                rsum += p;
            }
#pragma unroll
            for (int o = 8; o >= 1; o >>= 1)
                rsum += __shfl_xor_sync(0xffffffffu, rsum, o);
            l_st[i] = l_st[i] * alpha + rsum;
            m_st[i] = mnew;
#pragma unroll
            for (int c = 0; c < 8; c++) oacc[i][c] *= alpha;
        }
        __syncthreads();

        // O += P * V   (4 rows x 8 cols per thread)
        for (int kk = 0; kk < 64; kk++) {
            float pv[4];
#pragma unroll
            for (int i = 0; i < 4; i++) pv[i] = Ps[(ty * 4 + i) * 64 + kk];
            float4 v0 = *(float4*)&Vs[kk * 128 + tx * 8];
            float4 v1 = *(float4*)&Vs[kk * 128 + tx * 8 + 4];
#pragma unroll
            for (int i = 0; i < 4; i++) {
                oacc[i][0] += pv[i] * v0.x;
                oacc[i][1] += pv[i] * v0.y;
                oacc[i][2] += pv[i] * v0.z;
                oacc[i][3] += pv[i] * v0.w;
                oacc[i][4] += pv[i] * v1.x;
                oacc[i][5] += pv[i] * v1.y;
                oacc[i][6] += pv[i] * v1.z;
                oacc[i][7] += pv[i] * v1.w;
            }
        }
    }

    // Epilogue: normalize and write [B,S,H,HD] -> flat [B,S,D]
#pragma unroll
    for (int i = 0; i < 4; i++) {
        float inv = 1.f / l_st[i];
        float4 o0, o1;
        o0.x = oacc[i][0] * inv; o0.y = oacc[i][1] * inv;
        o0.z = oacc[i][2] * inv; o0.w = oacc[i][3] * inv;
        o1.x = oacc[i][4] * inv; o1.y = oacc[i][5] * inv;
        o1.z = oacc[i][6] * inv; o1.w = oacc[i][7] * inv;
        size_t g = base + (size_t)(q0 + ty * 4 + i) * ND + tx * 8;
        *(float4*)&g_attn[g] = o0;
        *(float4*)&g_attn[g + 4] = o1;
    }
}

// ---------------------------------------------------------------------------
extern "C" void kernel_launch(void* const* d_in, const int* in_sizes, int n_in,
                              void* d_out, int out_size)
{
    (void)in_sizes; (void)n_in; (void)out_size;
    const float* x    = (const float*)d_in[0];
    const float* wq   = (const float*)d_in[1];
    const float* wk   = (const float*)d_in[2];
    const float* wv   = (const float*)d_in[3];
    const float* wo   = (const float*)d_in[4];
    const float* fcos = (const float*)d_in[5];
    const float* fsin = (const float*)d_in[6];
    // d_in[7] = mask: causal tril, implemented directly in attn_kernel
    float* out = (float*)d_out;

    const int ATT_SMEM = (64 * 128 + 64 * 132 + 64 * 128 + 64 * 64) * 4; // 115712
    cudaFuncSetAttribute(attn_kernel,
                         cudaFuncAttributeMaxDynamicSharedMemorySize, ATT_SMEM);

    // 1) QKV projections (fused across grid.z)
    dim3 gqkv(32, 32, 3);
    gemm_tf32_kernel<<<gqkv, 256>>>(x, wq, wk, wv, nullptr, 0);

    // 2) RoPE on q and k (in-place; deterministic: GEMM rewrites scratch each replay)
    rope_kernel<<<65536, 256>>>(fcos, fsin);

    // 3) Causal flash attention
    dim3 gatt(NS / 64, NH, NB);
    attn_kernel<<<gatt, 256, ATT_SMEM>>>();

    // 4) Output projection
    dim3 go(32, 32, 1);
    gemm_tf32_kernel<<<go, 256>>>(nullptr, wo, wo, wo, out, 1);
}

// round 4
// speedup vs baseline: 1.2065x; 1.2065x over previous
#include <cuda_runtime.h>
#include <cuda_bf16.h>
#include <mma.h>
#include <cstdint>

using namespace nvcuda;

// Problem shape (fixed): B=4, S=1024, D=4096, H=32, HD=128
#define NB 4
#define NS 1024
#define ND 4096
#define NH 32
#define NHD 128
#define NTOK (NB * NS)          // 4096 rows

// Scratch (device globals: the sanctioned no-alloc workaround). 4 x 64MB.
__device__ float g_q[(size_t)NTOK * ND];
__device__ float g_k[(size_t)NTOK * ND];
__device__ float g_v[(size_t)NTOK * ND];
__device__ float g_attn[(size_t)NTOK * ND];

__device__ __forceinline__ void cp_async16(unsigned int dst, const void* src) {
    asm volatile("cp.async.cg.shared.global [%0], [%1], 16;\n" ::"r"(dst), "l"(src));
}

// ---------------------------------------------------------------------------
// GEMM: C[m,n] = sum_k A[m,k] * W[n,k]   (A: [4096,4096] rm, W: [4096,4096] rm)
// tf32 wmma m16n16k8. Block tile 128x128x32, 256 threads = 8 warps (2x4),
// each warp 64x32 = 4x2 fragments. 2-stage cp.async software pipeline.
// mode 0: A = A_ext, C = {g_q, g_k, g_v}[blockIdx.z], W = {W0,W1,W2}
// mode 1: A = g_attn, C = C_ext, W = W0
// ---------------------------------------------------------------------------
__global__ __launch_bounds__(256) void gemm_tf32_kernel(
    const float* __restrict__ A_ext,
    const float* __restrict__ W0, const float* __restrict__ W1,
    const float* __restrict__ W2,
    float* __restrict__ C_ext, int mode)
{
    constexpr int LD = 40;            // 32 + 8 pad, 160B rows (16B-aligned)
    constexpr int STAGE = 128 * LD * 2;  // floats per stage (As + Bs)
    extern __shared__ float sm[];     // 2 stages = 81920 bytes

    const int z = blockIdx.z;
    const float* W = (z == 0) ? W0 : (z == 1) ? W1 : W2;
    const float* A;
    float* C;
    if (mode == 0) {
        A = A_ext;
        C = (z == 0) ? g_q : (z == 1) ? g_k : g_v;
    } else {
        A = g_attn;
        C = C_ext;
    }

    const int tid = threadIdx.x;
    const int m0 = blockIdx.y * 128;
    const int n0 = blockIdx.x * 128;
    const int warp = tid >> 5;
    const int wm = warp >> 2;   // 0..1
    const int wn = warp & 3;    // 0..3

    // Per-thread copy coordinates (32 rows apart per chunk)
    const int cr = tid >> 3;          // 0..31
    const int cc = (tid & 7) << 2;    // 0,4,..,28

    wmma::fragment<wmma::accumulator, 16, 16, 8, float> acc[4][2];
#pragma unroll
    for (int i = 0; i < 4; i++)
#pragma unroll
        for (int j = 0; j < 2; j++)
            wmma::fill_fragment(acc[i][j], 0.0f);

    // Issue async copies of k-tile k0 into stage s
    auto issue = [&](int s, int k0) {
        float* As = sm + s * STAGE;
        float* Bs = As + 128 * LD;
#pragma unroll
        for (int t = 0; t < 4; t++) {
            int r = cr + t * 32;
            unsigned int da =
                (unsigned int)__cvta_generic_to_shared(&As[r * LD + cc]);
            cp_async16(da, &A[(size_t)(m0 + r) * ND + k0 + cc]);
            unsigned int db =
                (unsigned int)__cvta_generic_to_shared(&Bs[r * LD + cc]);
            cp_async16(db, &W[(size_t)(n0 + r) * ND + k0 + cc]);
        }
        asm volatile("cp.async.commit_group;\n" ::);
    };

    issue(0, 0);
    int s = 0;
    constexpr int KT = ND / 32;  // 128 k-tiles

    for (int kt = 0; kt < KT; kt++) {
        if (kt + 1 < KT) {
            issue(s ^ 1, (kt + 1) * 32);
            asm volatile("cp.async.wait_group 1;\n" ::);
        } else {
            asm volatile("cp.async.wait_group 0;\n" ::);
        }
        __syncthreads();

        const float* As = sm + s * STAGE;
        const float* Bs = As + 128 * LD;
#pragma unroll
        for (int kk = 0; kk < 32; kk += 8) {
            wmma::fragment<wmma::matrix_a, 16, 16, 8, wmma::precision::tf32,
                           wmma::row_major> af[4];
            wmma::fragment<wmma::matrix_b, 16, 16, 8, wmma::precision::tf32,
                           wmma::col_major> bf[2];
#pragma unroll
            for (int i = 0; i < 4; i++) {
                wmma::load_matrix_sync(af[i], &As[(wm * 64 + i * 16) * LD + kk], LD);
#pragma unroll
                for (int t = 0; t < af[i].num_elements; t++)
                    af[i].x[t] = wmma::__float_to_tf32(af[i].x[t]);
            }
#pragma unroll
            for (int j = 0; j < 2; j++) {
                wmma::load_matrix_sync(bf[j], &Bs[(wn * 32 + j * 16) * LD + kk], LD);
#pragma unroll
                for (int t = 0; t < bf[j].num_elements; t++)
                    bf[j].x[t] = wmma::__float_to_tf32(bf[j].x[t]);
            }
#pragma unroll
            for (int i = 0; i < 4; i++)
#pragma unroll
                for (int j = 0; j < 2; j++)
                    wmma::mma_sync(acc[i][j], af[i], bf[j], acc[i][j]);
        }
        __syncthreads();   // all warps done reading stage s before it is refilled
        s ^= 1;
    }

#pragma unroll
    for (int i = 0; i < 4; i++)
#pragma unroll
        for (int j = 0; j < 2; j++)
            wmma::store_matrix_sync(
                &C[(size_t)(m0 + wm * 64 + i * 16) * ND + n0 + wn * 32 + j * 16],
                acc[i][j], ND, wmma::mem_row_major);
}

// ---------------------------------------------------------------------------
// RoPE, in-place on g_q and g_k. One thread per (re,im) pair.
// ---------------------------------------------------------------------------
__global__ void rope_kernel(const float* __restrict__ fcos,
                            const float* __restrict__ fsin)
{
    int gid = blockIdx.x * blockDim.x + threadIdx.x;
    float* t = (gid < (1 << 23)) ? g_q : g_k;
    int p = gid & ((1 << 23) - 1);
    int row = p >> 11;           // 2048 pairs per row
    int pair = p & 2047;
    int i = pair & 63;           // pair index within head (HD/2 = 64)
    int s = row & 1023;          // sequence position
    float c = fcos[s * 64 + i];
    float sn = fsin[s * 64 + i];
    float2 v = *(float2*)&t[(size_t)row * ND + pair * 2];
    float2 o;
    o.x = v.x * c - v.y * sn;
    o.y = v.x * sn + v.y * c;
    *(float2*)&t[(size_t)row * ND + pair * 2] = o;
}

// ---------------------------------------------------------------------------
// Flash attention (online softmax), causal. Grid: (S/64, H, B). 256 threads
// as 16x16: thread (ty,tx) owns score rows ty*4..+4, score cols tx+16j (j<4),
// and O cols tx*8..+8. Tiles of 64 keys. Dynamic smem = 113 KB.
// ---------------------------------------------------------------------------
__global__ __launch_bounds__(256, 2) void attn_kernel()
{
    extern __shared__ float sma[];
    float* Qs = sma;                  // 64*128
    float* Ks = Qs + 64 * 128;        // 64*132 (pad 4 vs strided col reads)
    float* Vs = Ks + 64 * 132;        // 64*128
    float* Ps = Vs + 64 * 128;        // 64*64

    const int tid = threadIdx.x;
    const int ty = tid >> 4;
    const int tx = tid & 15;
    const int qt = blockIdx.x;
    const int h = blockIdx.y;
    const int b = blockIdx.z;
    const int q0 = qt * 64;

    const float scale = 0.08838834764831845f;  // 1/sqrt(128)
    const size_t base = (size_t)b * NS * ND + (size_t)h * NHD;

    // Load Q tile, pre-scaled
#pragma unroll
    for (int t = 0; t < 8; t++) {
        int e = tid + t * 256;
        int r = e >> 5;
        int c4 = (e & 31) << 2;
        float4 v = *(const float4*)&g_q[base + (size_t)(q0 + r) * ND + c4];
        v.x *= scale; v.y *= scale; v.z *= scale; v.w *= scale;
        *(float4*)&Qs[r * 128 + c4] = v;
    }

    float m_st[4], l_st[4], oacc[4][8];
#pragma unroll
    for (int i = 0; i < 4; i++) {
        m_st[i] = -1e30f;
        l_st[i] = 0.f;
#pragma unroll
        for (int c = 0; c < 8; c++) oacc[i][c] = 0.f;
    }

    for (int jt = 0; jt <= qt; jt++) {
        __syncthreads();  // protects Qs(first iter) & Ks/Vs/Ps from prior readers
#pragma unroll
        for (int t = 0; t < 8; t++) {
            int e = tid + t * 256;
            int r = e >> 5;
            int c4 = (e & 31) << 2;
            size_t g = base + (size_t)(jt * 64 + r) * ND + c4;
            *(float4*)&Ks[r * 132 + c4] = *(const float4*)&g_k[g];
            *(float4*)&Vs[r * 128 + c4] = *(const float4*)&g_v[g];
        }
        __syncthreads();

        // S = Qs * Ks^T   (4x4 per thread)
        float s[4][4];
#pragma unroll
        for (int i = 0; i < 4; i++)
#pragma unroll
            for (int j = 0; j < 4; j++) s[i][j] = 0.f;

        for (int d = 0; d < 128; d += 4) {
            float4 qv[4], kv[4];
#pragma unroll
            for (int i = 0; i < 4; i++)
                qv[i] = *(float4*)&Qs[(ty * 4 + i) * 128 + d];
#pragma unroll
            for (int j = 0; j < 4; j++)
                kv[j] = *(float4*)&Ks[(tx + 16 * j) * 132 + d];
#pragma unroll
            for (int i = 0; i < 4; i++)
#pragma unroll
                for (int j = 0; j < 4; j++)
                    s[i][j] += qv[i].x * kv[j].x + qv[i].y * kv[j].y +
                               qv[i].z * kv[j].z + qv[i].w * kv[j].w;
        }

        // Causal mask: only the diagonal tile needs elementwise masking
        if (jt == qt) {
#pragma unroll
            for (int i = 0; i < 4; i++)
#pragma unroll
                for (int j = 0; j < 4; j++)
                    if (tx + 16 * j > ty * 4 + i) s[i][j] = -1e30f;
        }

        // Online softmax (row reduce over tx = 16 lanes within each warp half)
#pragma unroll
        for (int i = 0; i < 4; i++) {
            float mx = fmaxf(fmaxf(s[i][0], s[i][1]), fmaxf(s[i][2], s[i][3]));
#pragma unroll
            for (int o = 8; o >= 1; o >>= 1)
                mx = fmaxf(mx, __shfl_xor_sync(0xffffffffu, mx, o));
            float mnew = fmaxf(m_st[i], mx);
            float alpha = __expf(m_st[i] - mnew);
            float rsum = 0.f;
#pragma unroll
            for (int j = 0; j < 4; j++) {
                float p = __expf(s[i][j] - mnew);
                Ps[(ty * 4 + i) * 64 + tx + 16 * j] = p;
                rsum += p;
            }
#pragma unroll
            for (int o = 8; o >= 1; o >>= 1)
                rsum += __shfl_xor_sync(0xffffffffu, rsum, o);
            l_st[i] = l_st[i] * alpha + rsum;
            m_st[i] = mnew;
#pragma unroll
            for (int c = 0; c < 8; c++) oacc[i][c] *= alpha;
        }
        __syncthreads();

        // O += P * V   (4 rows x 8 cols per thread)
        for (int kk = 0; kk < 64; kk++) {
            float pv[4];
#pragma unroll
            for (int i = 0; i < 4; i++) pv[i] = Ps[(ty * 4 + i) * 64 + kk];
            float4 v0 = *(float4*)&Vs[kk * 128 + tx * 8];
            float4 v1 = *(float4*)&Vs[kk * 128 + tx * 8 + 4];
#pragma unroll
            for (int i = 0; i < 4; i++) {
                oacc[i][0] += pv[i] * v0.x;
                oacc[i][1] += pv[i] * v0.y;
                oacc[i][2] += pv[i] * v0.z;
                oacc[i][3] += pv[i] * v0.w;
                oacc[i][4] += pv[i] * v1.x;
                oacc[i][5] += pv[i] * v1.y;
                oacc[i][6] += pv[i] * v1.z;
                oacc[i][7] += pv[i] * v1.w;
            }
        }
    }

    // Epilogue: normalize and write [B,S,H,HD] -> flat [B,S,D]
#pragma unroll
    for (int i = 0; i < 4; i++) {
        float inv = 1.f / l_st[i];
        float4 o0, o1;
        o0.x = oacc[i][0] * inv; o0.y = oacc[i][1] * inv;
        o0.z = oacc[i][2] * inv; o0.w = oacc[i][3] * inv;
        o1.x = oacc[i][4] * inv; o1.y = oacc[i][5] * inv;
        o1.z = oacc[i][6] * inv; o1.w = oacc[i][7] * inv;
        size_t g = base + (size_t)(q0 + ty * 4 + i) * ND + tx * 8;
        *(float4*)&g_attn[g] = o0;
        *(float4*)&g_attn[g + 4] = o1;
    }
}

// ---------------------------------------------------------------------------
extern "C" void kernel_launch(void* const* d_in, const int* in_sizes, int n_in,
                              void* d_out, int out_size)
{
    (void)in_sizes; (void)n_in; (void)out_size;
    const float* x    = (const float*)d_in[0];
    const float* wq   = (const float*)d_in[1];
    const float* wk   = (const float*)d_in[2];
    const float* wv   = (const float*)d_in[3];
    const float* wo   = (const float*)d_in[4];
    const float* fcos = (const float*)d_in[5];
    const float* fsin = (const float*)d_in[6];
    // d_in[7] = mask: causal tril, implemented directly in attn_kernel
    float* out = (float*)d_out;

    const int GEMM_SMEM = 2 * 128 * 40 * 2 * 4;  // 81920 B (2 stages, As+Bs)
    cudaFuncSetAttribute(gemm_tf32_kernel,
                         cudaFuncAttributeMaxDynamicSharedMemorySize, GEMM_SMEM);

    const int ATT_SMEM = (64 * 128 + 64 * 132 + 64 * 128 + 64 * 64) * 4; // 115712
    cudaFuncSetAttribute(attn_kernel,
                         cudaFuncAttributeMaxDynamicSharedMemorySize, ATT_SMEM);

    // 1) QKV projections (fused across grid.z)
    dim3 gqkv(32, 32, 3);
    gemm_tf32_kernel<<<gqkv, 256, GEMM_SMEM>>>(x, wq, wk, wv, nullptr, 0);

    // 2) RoPE on q and k (in-place; deterministic: GEMM rewrites scratch each replay)
    rope_kernel<<<65536, 256>>>(fcos, fsin);

    // 3) Causal flash attention
    dim3 gatt(NS / 64, NH, NB);
    attn_kernel<<<gatt, 256, ATT_SMEM>>>();

    // 4) Output projection
    dim3 go(32, 32, 1);
    gemm_tf32_kernel<<<go, 256, GEMM_SMEM>>>(nullptr, wo, wo, wo, out, 1);
}

// round 9
// speedup vs baseline: 1.2322x; 1.0213x over previous
#include <cuda_runtime.h>
#include <cuda_bf16.h>
#include <mma.h>
#include <cstdint>

using namespace nvcuda;

// Problem shape (fixed): B=4, S=1024, D=4096, H=32, HD=128
#define NB 4
#define NS 1024
#define ND 4096
#define NH 32
#define NHD 128
#define NTOK (NB * NS)          // 4096 rows

// Scratch (device globals: the sanctioned no-alloc workaround). 4 x 64MB.
__device__ float g_q[(size_t)NTOK * ND];
__device__ float g_k[(size_t)NTOK * ND];
__device__ float g_v[(size_t)NTOK * ND];
__device__ float g_attn[(size_t)NTOK * ND];

__device__ __forceinline__ void cp_async16(unsigned int dst, const void* src) {
    asm volatile("cp.async.cg.shared.global [%0], [%1], 16;\n" ::"r"(dst), "l"(src));
}

// ---------------------------------------------------------------------------
// GEMM: C[m,n] = sum_k A[m,k] * W[n,k]   (A: [4096,4096] rm, W: [4096,4096] rm)
// tf32 wmma m16n16k8. Block tile 128x128x32, 256 threads = 8 warps (2x4),
// each warp 64x32 = 4x2 fragments. 2-stage cp.async software pipeline.
// __launch_bounds__(256, 2): cap regs at 128 so TWO blocks fit per SM
// (2 x 81920 B smem = 163840 B < 227 KB; reg file was the old limiter).
// mode 0: A = A_ext, C = {g_q, g_k, g_v}[blockIdx.z], W = {W0,W1,W2}
// mode 1: A = g_attn, C = C_ext, W = W0
// ---------------------------------------------------------------------------
__global__ __launch_bounds__(256, 2) void gemm_tf32_kernel(
    const float* __restrict__ A_ext,
    const float* __restrict__ W0, const float* __restrict__ W1,
    const float* __restrict__ W2,
    float* __restrict__ C_ext, int mode)
{
    constexpr int LD = 40;            // 32 + 8 pad, 160B rows (16B-aligned)
    constexpr int STAGE = 128 * LD * 2;  // floats per stage (As + Bs)
    extern __shared__ float sm[];     // 2 stages = 81920 bytes

    const int z = blockIdx.z;
    const float* W = (z == 0) ? W0 : (z == 1) ? W1 : W2;
    const float* A;
    float* C;
    if (mode == 0) {
        A = A_ext;
        C = (z == 0) ? g_q : (z == 1) ? g_k : g_v;
    } else {
        A = g_attn;
        C = C_ext;
    }

    const int tid = threadIdx.x;
    const int m0 = blockIdx.y * 128;
    const int n0 = blockIdx.x * 128;
    const int warp = tid >> 5;
    const int wm = warp >> 2;   // 0..1
    const int wn = warp & 3;    // 0..3

    // Per-thread copy coordinates (32 rows apart per chunk)
    const int cr = tid >> 3;          // 0..31
    const int cc = (tid & 7) << 2;    // 0,4,..,28

    wmma::fragment<wmma::accumulator, 16, 16, 8, float> acc[4][2];
#pragma unroll
    for (int i = 0; i < 4; i++)
#pragma unroll
        for (int j = 0; j < 2; j++)
            wmma::fill_fragment(acc[i][j], 0.0f);

    // Issue async copies of k-tile k0 into stage s
    auto issue = [&](int s, int k0) {
        float* As = sm + s * STAGE;
        float* Bs = As + 128 * LD;
#pragma unroll
        for (int t = 0; t < 4; t++) {
            int r = cr + t * 32;
            unsigned int da =
                (unsigned int)__cvta_generic_to_shared(&As[r * LD + cc]);
            cp_async16(da, &A[(size_t)(m0 + r) * ND + k0 + cc]);
            unsigned int db =
                (unsigned int)__cvta_generic_to_shared(&Bs[r * LD + cc]);
            cp_async16(db, &W[(size_t)(n0 + r) * ND + k0 + cc]);
        }
        asm volatile("cp.async.commit_group;\n" ::);
    };

    issue(0, 0);
    int s = 0;
    constexpr int KT = ND / 32;  // 128 k-tiles

    for (int kt = 0; kt < KT; kt++) {
        if (kt + 1 < KT) {
            issue(s ^ 1, (kt + 1) * 32);
            asm volatile("cp.async.wait_group 1;\n" ::);
        } else {
            asm volatile("cp.async.wait_group 0;\n" ::);
        }
        __syncthreads();

        const float* As = sm + s * STAGE;
        const float* Bs = As + 128 * LD;
#pragma unroll
        for (int kk = 0; kk < 32; kk += 8) {
            wmma::fragment<wmma::matrix_a, 16, 16, 8, wmma::precision::tf32,
                           wmma::row_major> af[4];
            wmma::fragment<wmma::matrix_b, 16, 16, 8, wmma::precision::tf32,
                           wmma::col_major> bf[2];
#pragma unroll
            for (int i = 0; i < 4; i++) {
                wmma::load_matrix_sync(af[i], &As[(wm * 64 + i * 16) * LD + kk], LD);
#pragma unroll
                for (int t = 0; t < af[i].num_elements; t++)
                    af[i].x[t] = wmma::__float_to_tf32(af[i].x[t]);
            }
#pragma unroll
            for (int j = 0; j < 2; j++) {
                wmma::load_matrix_sync(bf[j], &Bs[(wn * 32 + j * 16) * LD + kk], LD);
#pragma unroll
                for (int t = 0; t < bf[j].num_elements; t++)
                    bf[j].x[t] = wmma::__float_to_tf32(bf[j].x[t]);
            }
#pragma unroll
            for (int i = 0; i < 4; i++)
#pragma unroll
                for (int j = 0; j < 2; j++)
                    wmma::mma_sync(acc[i][j], af[i], bf[j], acc[i][j]);
        }
        __syncthreads();   // all warps done reading stage s before it is refilled
        s ^= 1;
    }

#pragma unroll
    for (int i = 0; i < 4; i++)
#pragma unroll
        for (int j = 0; j < 2; j++)
            wmma::store_matrix_sync(
                &C[(size_t)(m0 + wm * 64 + i * 16) * ND + n0 + wn * 32 + j * 16],
                acc[i][j], ND, wmma::mem_row_major);
}

// ---------------------------------------------------------------------------
// RoPE, in-place on g_q and g_k. One thread per (re,im) pair.
// ---------------------------------------------------------------------------
__global__ void rope_kernel(const float* __restrict__ fcos,
                            const float* __restrict__ fsin)
{
    int gid = blockIdx.x * blockDim.x + threadIdx.x;
    float* t = (gid < (1 << 23)) ? g_q : g_k;
    int p = gid & ((1 << 23) - 1);
    int row = p >> 11;           // 2048 pairs per row
    int pair = p & 2047;
    int i = pair & 63;           // pair index within head (HD/2 = 64)
    int s = row & 1023;          // sequence position
    float c = fcos[s * 64 + i];
    float sn = fsin[s * 64 + i];
    float2 v = *(float2*)&t[(size_t)row * ND + pair * 2];
    float2 o;
    o.x = v.x * c - v.y * sn;
    o.y = v.x * sn + v.y * c;
    *(float2*)&t[(size_t)row * ND + pair * 2] = o;
}

// ---------------------------------------------------------------------------
// Flash attention (online softmax), causal. Grid: (S/64, H, B). 256 threads
// as 16x16: thread (ty,tx) owns score rows ty*4..+4, score cols tx+16j (j<4),
// and O cols tx*8..+8. Tiles of 64 keys. Dynamic smem = 113 KB.
// ---------------------------------------------------------------------------
__global__ __launch_bounds__(256, 2) void attn_kernel()
{
    extern __shared__ float sma[];
    float* Qs = sma;                  // 64*128
    float* Ks = Qs + 64 * 128;        // 64*132 (pad 4 vs strided col reads)
    float* Vs = Ks + 64 * 132;        // 64*128
    float* Ps = Vs + 64 * 128;        // 64*64

    const int tid = threadIdx.x;
    const int ty = tid >> 4;
    const int tx = tid & 15;
    const int qt = blockIdx.x;
    const int h = blockIdx.y;
    const int b = blockIdx.z;
    const int q0 = qt * 64;

    const float scale = 0.08838834764831845f;  // 1/sqrt(128)
    const size_t base = (size_t)b * NS * ND + (size_t)h * NHD;

    // Load Q tile, pre-scaled
#pragma unroll
    for (int t = 0; t < 8; t++) {
        int e = tid + t * 256;
        int r = e >> 5;
        int c4 = (e & 31) << 2;
        float4 v = *(const float4*)&g_q[base + (size_t)(q0 + r) * ND + c4];
        v.x *= scale; v.y *= scale; v.z *= scale; v.w *= scale;
        *(float4*)&Qs[r * 128 + c4] = v;
    }

    float m_st[4], l_st[4], oacc[4][8];
#pragma unroll
    for (int i = 0; i < 4; i++) {
        m_st[i] = -1e30f;
        l_st[i] = 0.f;
#pragma unroll
        for (int c = 0; c < 8; c++) oacc[i][c] = 0.f;
    }

    for (int jt = 0; jt <= qt; jt++) {
        __syncthreads();  // protects Qs(first iter) & Ks/Vs/Ps from prior readers
#pragma unroll
        for (int t = 0; t < 8; t++) {
            int e = tid + t * 256;
            int r = e >> 5;
            int c4 = (e & 31) << 2;
            size_t g = base + (size_t)(jt * 64 + r) * ND + c4;
            *(float4*)&Ks[r * 132 + c4] = *(const float4*)&g_k[g];
            *(float4*)&Vs[r * 128 + c4] = *(const float4*)&g_v[g];
        }
        __syncthreads();

        // S = Qs * Ks^T   (4x4 per thread)
        float s[4][4];
#pragma unroll
        for (int i = 0; i < 4; i++)
#pragma unroll
            for (int j = 0; j < 4; j++) s[i][j] = 0.f;

        for (int d = 0; d < 128; d += 4) {
            float4 qv[4], kv[4];
#pragma unroll
            for (int i = 0; i < 4; i++)
                qv[i] = *(float4*)&Qs[(ty * 4 + i) * 128 + d];
#pragma unroll
            for (int j = 0; j < 4; j++)
                kv[j] = *(float4*)&Ks[(tx + 16 * j) * 132 + d];
#pragma unroll
            for (int i = 0; i < 4; i++)
#pragma unroll
                for (int j = 0; j < 4; j++)
                    s[i][j] += qv[i].x * kv[j].x + qv[i].y * kv[j].y +
                               qv[i].z * kv[j].z + qv[i].w * kv[j].w;
        }

        // Causal mask: only the diagonal tile needs elementwise masking
        if (jt == qt) {
#pragma unroll
            for (int i = 0; i < 4; i++)
#pragma unroll
                for (int j = 0; j < 4; j++)
                    if (tx + 16 * j > ty * 4 + i) s[i][j] = -1e30f;
        }

        // Online softmax (row reduce over tx = 16 lanes within each warp half)
#pragma unroll
        for (int i = 0; i < 4; i++) {
            float mx = fmaxf(fmaxf(s[i][0], s[i][1]), fmaxf(s[i][2], s[i][3]));
#pragma unroll
            for (int o = 8; o >= 1; o >>= 1)
                mx = fmaxf(mx, __shfl_xor_sync(0xffffffffu, mx, o));
            float mnew = fmaxf(m_st[i], mx);
            float alpha = __expf(m_st[i] - mnew);
            float rsum = 0.f;
#pragma unroll
            for (int j = 0; j < 4; j++) {
                float p = __expf(s[i][j] - mnew);
                Ps[(ty * 4 + i) * 64 + tx + 16 * j] = p;
                rsum += p;
            }
#pragma unroll
            for (int o = 8; o >= 1; o >>= 1)
                rsum += __shfl_xor_sync(0xffffffffu, rsum, o);
            l_st[i] = l_st[i] * alpha + rsum;
            m_st[i] = mnew;
#pragma unroll
            for (int c = 0; c < 8; c++) oacc[i][c] *= alpha;
        }
        __syncthreads();

        // O += P * V   (4 rows x 8 cols per thread)
        for (int kk = 0; kk < 64; kk++) {
            float pv[4];
#pragma unroll
            for (int i = 0; i < 4; i++) pv[i] = Ps[(ty * 4 + i) * 64 + kk];
            float4 v0 = *(float4*)&Vs[kk * 128 + tx * 8];
            float4 v1 = *(float4*)&Vs[kk * 128 + tx * 8 + 4];
#pragma unroll
            for (int i = 0; i < 4; i++) {
                oacc[i][0] += pv[i] * v0.x;
                oacc[i][1] += pv[i] * v0.y;
                oacc[i][2] += pv[i] * v0.z;
                oacc[i][3] += pv[i] * v0.w;
                oacc[i][4] += pv[i] * v1.x;
                oacc[i][5] += pv[i] * v1.y;
                oacc[i][6] += pv[i] * v1.z;
                oacc[i][7] += pv[i] * v1.w;
            }
        }
    }

    // Epilogue: normalize and write [B,S,H,HD] -> flat [B,S,D]
#pragma unroll
    for (int i = 0; i < 4; i++) {
        float inv = 1.f / l_st[i];
        float4 o0, o1;
        o0.x = oacc[i][0] * inv; o0.y = oacc[i][1] * inv;
        o0.z = oacc[i][2] * inv; o0.w = oacc[i][3] * inv;
        o1.x = oacc[i][4] * inv; o1.y = oacc[i][5] * inv;
        o1.z = oacc[i][6] * inv; o1.w = oacc[i][7] * inv;
        size_t g = base + (size_t)(q0 + ty * 4 + i) * ND + tx * 8;
        *(float4*)&g_attn[g] = o0;
        *(float4*)&g_attn[g + 4] = o1;
    }
}

// ---------------------------------------------------------------------------
extern "C" void kernel_launch(void* const* d_in, const int* in_sizes, int n_in,
                              void* d_out, int out_size)
{
    (void)in_sizes; (void)n_in; (void)out_size;
    const float* x    = (const float*)d_in[0];
    const float* wq   = (const float*)d_in[1];
    const float* wk   = (const float*)d_in[2];
    const float* wv   = (const float*)d_in[3];
    const float* wo   = (const float*)d_in[4];
    const float* fcos = (const float*)d_in[5];
    const float* fsin = (const float*)d_in[6];
    // d_in[7] = mask: causal tril, implemented directly in attn_kernel
    float* out = (float*)d_out;

    const int GEMM_SMEM = 2 * 128 * 40 * 2 * 4;  // 81920 B (2 stages, As+Bs)
    cudaFuncSetAttribute(gemm_tf32_kernel,
                         cudaFuncAttributeMaxDynamicSharedMemorySize, GEMM_SMEM);

    const int ATT_SMEM = (64 * 128 + 64 * 132 + 64 * 128 + 64 * 64) * 4; // 115712
    cudaFuncSetAttribute(attn_kernel,
                         cudaFuncAttributeMaxDynamicSharedMemorySize, ATT_SMEM);

    // 1) QKV projections (fused across grid.z)
    dim3 gqkv(32, 32, 3);
    gemm_tf32_kernel<<<gqkv, 256, GEMM_SMEM>>>(x, wq, wk, wv, nullptr, 0);

    // 2) RoPE on q and k (in-place; deterministic: GEMM rewrites scratch each replay)
    rope_kernel<<<65536, 256>>>(fcos, fsin);

    // 3) Causal flash attention
    dim3 gatt(NS / 64, NH, NB);
    attn_kernel<<<gatt, 256, ATT_SMEM>>>();

    // 4) Output projection
    dim3 go(32, 32, 1);
    gemm_tf32_kernel<<<go, 256, GEMM_SMEM>>>(nullptr, wo, wo, wo, out, 1);
}

// round 14
// speedup vs baseline: 1.4157x; 1.1489x over previous
#include <cuda_runtime.h>
#include <cuda_bf16.h>
#include <mma.h>
#include <cstdint>

using namespace nvcuda;

// Problem shape (fixed): B=4, S=1024, D=4096, H=32, HD=128
#define NB 4
#define NS 1024
#define ND 4096
#define NH 32
#define NHD 128
#define NTOK (NB * NS)          // 4096 rows

// Scratch (device globals: the sanctioned no-alloc workaround). 4 x 64MB.
__device__ float g_q[(size_t)NTOK * ND];
__device__ float g_k[(size_t)NTOK * ND];
__device__ float g_v[(size_t)NTOK * ND];
__device__ float g_attn[(size_t)NTOK * ND];

__device__ __forceinline__ void cp_async16(unsigned int dst, const void* src) {
    asm volatile("cp.async.cg.shared.global [%0], [%1], 16;\n" ::"r"(dst), "l"(src));
}

// ---------------------------------------------------------------------------
// GEMM: C[m,n] = sum_k A[m,k] * W[n,k]   (A: [4096,4096] rm, W: [4096,4096] rm)
// tf32 wmma m16n16k8. Block tile 128x128x32 with 128 threads = 4 warps (2x2),
// each warp 64x64 = 4x4 fragments: 8 fragment loads per 16 MMAs (0.5/MMA)
// vs 6 per 8 (0.75/MMA) in the old 8-warp 64x32 layout -> 1.5x less smem
// crossbar + convert traffic per MAC, with the SAME 81920 B smem footprint
// that has passed repeatedly. ~190 regs x 128 thr -> 2 blocks/SM resident.
// 2-stage cp.async software pipeline (proven structure).
// mode 0: A = A_ext, C = {g_q, g_k, g_v}[blockIdx.z], W = {W0,W1,W2}
// mode 1: A = g_attn, C = C_ext, W = W0
// ---------------------------------------------------------------------------
__global__ __launch_bounds__(128) void gemm_tf32_kernel(
    const float* __restrict__ A_ext,
    const float* __restrict__ W0, const float* __restrict__ W1,
    const float* __restrict__ W2,
    float* __restrict__ C_ext, int mode)
{
    constexpr int LD = 40;               // 32 + 8 pad, 160B rows (16B-aligned)
    constexpr int STAGE = 128 * LD * 2;  // floats per stage (As + Bs)
    extern __shared__ float sm[];        // 2 stages = 81920 bytes

    const int z = blockIdx.z;
    const float* W = (z == 0) ? W0 : (z == 1) ? W1 : W2;
    const float* A;
    float* C;
    if (mode == 0) {
        A = A_ext;
        C = (z == 0) ? g_q : (z == 1) ? g_k : g_v;
    } else {
        A = g_attn;
        C = C_ext;
    }

    const int tid = threadIdx.x;
    const int m0 = blockIdx.y * 128;
    const int n0 = blockIdx.x * 128;
    const int warp = tid >> 5;       // 0..3
    const int wm = warp >> 1;        // 0..1 -> m offset wm*64
    const int wn = warp & 1;         // 0..1 -> n offset wn*64

    // Per-thread copy coordinates: 128 threads cover 16 rows x 8 float4 cols
    const int cr = tid >> 3;          // 0..15
    const int cc = (tid & 7) << 2;    // 0,4,..,28

    wmma::fragment<wmma::accumulator, 16, 16, 8, float> acc[4][4];
#pragma unroll
    for (int i = 0; i < 4; i++)
#pragma unroll
        for (int j = 0; j < 4; j++)
            wmma::fill_fragment(acc[i][j], 0.0f);

    // Issue async copies of k-tile k0 into stage s
    auto issue = [&](int s, int k0) {
        float* As = sm + s * STAGE;
        float* Bs = As + 128 * LD;
#pragma unroll
        for (int t = 0; t < 8; t++) {     // 8 rounds x 16 rows = 128 rows
            int r = cr + t * 16;
            unsigned int da =
                (unsigned int)__cvta_generic_to_shared(&As[r * LD + cc]);
            cp_async16(da, &A[(size_t)(m0 + r) * ND + k0 + cc]);
            unsigned int db =
                (unsigned int)__cvta_generic_to_shared(&Bs[r * LD + cc]);
            cp_async16(db, &W[(size_t)(n0 + r) * ND + k0 + cc]);
        }
        asm volatile("cp.async.commit_group;\n" ::);
    };

    issue(0, 0);
    int s = 0;
    constexpr int KT = ND / 32;  // 128 k-tiles

    for (int kt = 0; kt < KT; kt++) {
        if (kt + 1 < KT) {
            issue(s ^ 1, (kt + 1) * 32);
            asm volatile("cp.async.wait_group 1;\n" ::);
        } else {
            asm volatile("cp.async.wait_group 0;\n" ::);
        }
        __syncthreads();

        const float* As = sm + s * STAGE;
        const float* Bs = As + 128 * LD;
#pragma unroll
        for (int kk = 0; kk < 32; kk += 8) {
            wmma::fragment<wmma::matrix_a, 16, 16, 8, wmma::precision::tf32,
                           wmma::row_major> af[4];
            wmma::fragment<wmma::matrix_b, 16, 16, 8, wmma::precision::tf32,
                           wmma::col_major> bf[4];
#pragma unroll
            for (int i = 0; i < 4; i++) {
                wmma::load_matrix_sync(af[i], &As[(wm * 64 + i * 16) * LD + kk], LD);
#pragma unroll
                for (int t = 0; t < af[i].num_elements; t++)
                    af[i].x[t] = wmma::__float_to_tf32(af[i].x[t]);
            }
#pragma unroll
            for (int j = 0; j < 4; j++) {
                wmma::load_matrix_sync(bf[j], &Bs[(wn * 64 + j * 16) * LD + kk], LD);
#pragma unroll
                for (int t = 0; t < bf[j].num_elements; t++)
                    bf[j].x[t] = wmma::__float_to_tf32(bf[j].x[t]);
            }
#pragma unroll
            for (int i = 0; i < 4; i++)
#pragma unroll
                for (int j = 0; j < 4; j++)
                    wmma::mma_sync(acc[i][j], af[i], bf[j], acc[i][j]);
        }
        __syncthreads();   // all warps done reading stage s before it is refilled
        s ^= 1;
    }

#pragma unroll
    for (int i = 0; i < 4; i++)
#pragma unroll
        for (int j = 0; j < 4; j++)
            wmma::store_matrix_sync(
                &C[(size_t)(m0 + wm * 64 + i * 16) * ND + n0 + wn * 64 + j * 16],
                acc[i][j], ND, wmma::mem_row_major);
}

// ---------------------------------------------------------------------------
// RoPE, in-place on g_q and g_k. One thread per (re,im) pair.
// ---------------------------------------------------------------------------
__global__ void rope_kernel(const float* __restrict__ fcos,
                            const float* __restrict__ fsin)
{
    int gid = blockIdx.x * blockDim.x + threadIdx.x;
    float* t = (gid < (1 << 23)) ? g_q : g_k;
    int p = gid & ((1 << 23) - 1);
    int row = p >> 11;           // 2048 pairs per row
    int pair = p & 2047;
    int i = pair & 63;           // pair index within head (HD/2 = 64)
    int s = row & 1023;          // sequence position
    float c = fcos[s * 64 + i];
    float sn = fsin[s * 64 + i];
    float2 v = *(float2*)&t[(size_t)row * ND + pair * 2];
    float2 o;
    o.x = v.x * c - v.y * sn;
    o.y = v.x * sn + v.y * c;
    *(float2*)&t[(size_t)row * ND + pair * 2] = o;
}

// ---------------------------------------------------------------------------
// Flash attention (online softmax), causal. Grid: (S/64, H, B). 256 threads
// as 16x16: thread (ty,tx) owns score rows ty*4..+4, score cols tx+16j (j<4),
// and O cols tx*8..+8. Tiles of 64 keys. Dynamic smem = 113 KB.
// ---------------------------------------------------------------------------
__global__ __launch_bounds__(256, 2) void attn_kernel()
{
    extern __shared__ float sma[];
    float* Qs = sma;                  // 64*128
    float* Ks = Qs + 64 * 128;        // 64*132 (pad 4 vs strided col reads)
    float* Vs = Ks + 64 * 132;        // 64*128
    float* Ps = Vs + 64 * 128;        // 64*64

    const int tid = threadIdx.x;
    const int ty = tid >> 4;
    const int tx = tid & 15;
    const int qt = blockIdx.x;
    const int h = blockIdx.y;
    const int b = blockIdx.z;
    const int q0 = qt * 64;

    const float scale = 0.08838834764831845f;  // 1/sqrt(128)
    const size_t base = (size_t)b * NS * ND + (size_t)h * NHD;

    // Load Q tile, pre-scaled
#pragma unroll
    for (int t = 0; t < 8; t++) {
        int e = tid + t * 256;
        int r = e >> 5;
        int c4 = (e & 31) << 2;
        float4 v = *(const float4*)&g_q[base + (size_t)(q0 + r) * ND + c4];
        v.x *= scale; v.y *= scale; v.z *= scale; v.w *= scale;
        *(float4*)&Qs[r * 128 + c4] = v;
    }

    float m_st[4], l_st[4], oacc[4][8];
#pragma unroll
    for (int i = 0; i < 4; i++) {
        m_st[i] = -1e30f;
        l_st[i] = 0.f;
#pragma unroll
        for (int c = 0; c < 8; c++) oacc[i][c] = 0.f;
    }

    for (int jt = 0; jt <= qt; jt++) {
        __syncthreads();  // protects Qs(first iter) & Ks/Vs/Ps from prior readers
#pragma unroll
        for (int t = 0; t < 8; t++) {
            int e = tid + t * 256;
            int r = e >> 5;
            int c4 = (e & 31) << 2;
            size_t g = base + (size_t)(jt * 64 + r) * ND + c4;
            *(float4*)&Ks[r * 132 + c4] = *(const float4*)&g_k[g];
            *(float4*)&Vs[r * 128 + c4] = *(const float4*)&g_v[g];
        }
        __syncthreads();

        // S = Qs * Ks^T   (4x4 per thread)
        float s[4][4];
#pragma unroll
        for (int i = 0; i < 4; i++)
#pragma unroll
            for (int j = 0; j < 4; j++) s[i][j] = 0.f;

        for (int d = 0; d < 128; d += 4) {
            float4 qv[4], kv[4];
#pragma unroll
            for (int i = 0; i < 4; i++)
                qv[i] = *(float4*)&Qs[(ty * 4 + i) * 128 + d];
#pragma unroll
            for (int j = 0; j < 4; j++)
                kv[j] = *(float4*)&Ks[(tx + 16 * j) * 132 + d];
#pragma unroll
            for (int i = 0; i < 4; i++)
#pragma unroll
                for (int j = 0; j < 4; j++)
                    s[i][j] += qv[i].x * kv[j].x + qv[i].y * kv[j].y +
                               qv[i].z * kv[j].z + qv[i].w * kv[j].w;
        }

        // Causal mask: only the diagonal tile needs elementwise masking
        if (jt == qt) {
#pragma unroll
            for (int i = 0; i < 4; i++)
#pragma unroll
                for (int j = 0; j < 4; j++)
                    if (tx + 16 * j > ty * 4 + i) s[i][j] = -1e30f;
        }

        // Online softmax (row reduce over tx = 16 lanes within each warp half)
#pragma unroll
        for (int i = 0; i < 4; i++) {
            float mx = fmaxf(fmaxf(s[i][0], s[i][1]), fmaxf(s[i][2], s[i][3]));
#pragma unroll
            for (int o = 8; o >= 1; o >>= 1)
                mx = fmaxf(mx, __shfl_xor_sync(0xffffffffu, mx, o));
            float mnew = fmaxf(m_st[i], mx);
            float alpha = __expf(m_st[i] - mnew);
            float rsum = 0.f;
#pragma unroll
            for (int j = 0; j < 4; j++) {
                float p = __expf(s[i][j] - mnew);
                Ps[(ty * 4 + i) * 64 + tx + 16 * j] = p;
                rsum += p;
            }
#pragma unroll
            for (int o = 8; o >= 1; o >>= 1)
                rsum += __shfl_xor_sync(0xffffffffu, rsum, o);
            l_st[i] = l_st[i] * alpha + rsum;
            m_st[i] = mnew;
#pragma unroll
            for (int c = 0; c < 8; c++) oacc[i][c] *= alpha;
        }
        __syncthreads();

        // O += P * V   (4 rows x 8 cols per thread)
        for (int kk = 0; kk < 64; kk++) {
            float pv[4];
#pragma unroll
            for (int i = 0; i < 4; i++) pv[i] = Ps[(ty * 4 + i) * 64 + kk];
            float4 v0 = *(float4*)&Vs[kk * 128 + tx * 8];
            float4 v1 = *(float4*)&Vs[kk * 128 + tx * 8 + 4];
#pragma unroll
            for (int i = 0; i < 4; i++) {
                oacc[i][0] += pv[i] * v0.x;
                oacc[i][1] += pv[i] * v0.y;
                oacc[i][2] += pv[i] * v0.z;
                oacc[i][3] += pv[i] * v0.w;
                oacc[i][4] += pv[i] * v1.x;
                oacc[i][5] += pv[i] * v1.y;
                oacc[i][6] += pv[i] * v1.z;
                oacc[i][7] += pv[i] * v1.w;
            }
        }
    }

    // Epilogue: normalize and write [B,S,H,HD] -> flat [B,S,D]
#pragma unroll
    for (int i = 0; i < 4; i++) {
        float inv = 1.f / l_st[i];
        float4 o0, o1;
        o0.x = oacc[i][0] * inv; o0.y = oacc[i][1] * inv;
        o0.z = oacc[i][2] * inv; o0.w = oacc[i][3] * inv;
        o1.x = oacc[i][4] * inv; o1.y = oacc[i][5] * inv;
        o1.z = oacc[i][6] * inv; o1.w = oacc[i][7] * inv;
        size_t g = base + (size_t)(q0 + ty * 4 + i) * ND + tx * 8;
        *(float4*)&g_attn[g] = o0;
        *(float4*)&g_attn[g + 4] = o1;
    }
}

// ---------------------------------------------------------------------------
extern "C" void kernel_launch(void* const* d_in, const int* in_sizes, int n_in,
                              void* d_out, int out_size)
{
    (void)in_sizes; (void)n_in; (void)out_size;
    const float* x    = (const float*)d_in[0];
    const float* wq   = (const float*)d_in[1];
    const float* wk   = (const float*)d_in[2];
    const float* wv   = (const float*)d_in[3];
    const float* wo   = (const float*)d_in[4];
    const float* fcos = (const float*)d_in[5];
    const float* fsin = (const float*)d_in[6];
    // d_in[7] = mask: causal tril, implemented directly in attn_kernel
    float* out = (float*)d_out;

    const int GEMM_SMEM = 2 * 128 * 40 * 2 * 4;  // 81920 B (2 stages, As+Bs)
    cudaFuncSetAttribute(gemm_tf32_kernel,
                         cudaFuncAttributeMaxDynamicSharedMemorySize, GEMM_SMEM);

    const int ATT_SMEM = (64 * 128 + 64 * 132 + 64 * 128 + 64 * 64) * 4; // 115712
    cudaFuncSetAttribute(attn_kernel,
                         cudaFuncAttributeMaxDynamicSharedMemorySize, ATT_SMEM);

    // 1) QKV projections (fused across grid.z)
    dim3 gqkv(32, 32, 3);
    gemm_tf32_kernel<<<gqkv, 128, GEMM_SMEM>>>(x, wq, wk, wv, nullptr, 0);

    // 2) RoPE on q and k (in-place; deterministic: GEMM rewrites scratch each replay)
    rope_kernel<<<65536, 256>>>(fcos, fsin);

    // 3) Causal flash attention
    dim3 gatt(NS / 64, NH, NB);
    attn_kernel<<<gatt, 256, ATT_SMEM>>>();

    // 4) Output projection
    dim3 go(32, 32, 1);
    gemm_tf32_kernel<<<go, 128, GEMM_SMEM>>>(nullptr, wo, wo, wo, out, 1);
}

// round 15
// speedup vs baseline: 3.7526x; 2.6507x over previous
#include <cuda_runtime.h>
#include <cuda_fp16.h>
#include <cuda_bf16.h>
#include <mma.h>
#include <cstdint>

using namespace nvcuda;

// Problem shape (fixed): B=4, S=1024, D=4096, H=32, HD=128
#define NB 4
#define NS 1024
#define ND 4096
#define NH 32
#define NHD 128
#define NTOK (NB * NS)          // 4096 rows

// Scratch (device globals: the sanctioned no-alloc workaround).
__device__ float  g_q[(size_t)NTOK * ND];       // fp32 QKV outputs (rope/attn in fp32)
__device__ float  g_k[(size_t)NTOK * ND];
__device__ float  g_v[(size_t)NTOK * ND];
__device__ __half g_xh[(size_t)NTOK * ND];      // half inputs for GEMMs
__device__ __half g_wqh[(size_t)ND * ND];
__device__ __half g_wkh[(size_t)ND * ND];
__device__ __half g_wvh[(size_t)ND * ND];
__device__ __half g_woh[(size_t)ND * ND];
__device__ __half g_attnh[(size_t)NTOK * ND];   // attention output (half)

__device__ __forceinline__ void cp_async16(unsigned int dst, const void* src) {
    asm volatile("cp.async.cg.shared.global [%0], [%1], 16;\n" ::"r"(dst), "l"(src));
}

// ---------------------------------------------------------------------------
// fp32 -> fp16 convert pre-pass. grid = (4096, 1, 5); each block converts
// 4096 contiguous floats of the z-selected tensor. RN rounding = same 10-bit
// mantissa error as the old __float_to_tf32 path.
// ---------------------------------------------------------------------------
__global__ void f2h_kernel(const float* __restrict__ x,
                           const float* __restrict__ wq,
                           const float* __restrict__ wk,
                           const float* __restrict__ wv,
                           const float* __restrict__ wo)
{
    const float* src;
    __half* dst;
    switch (blockIdx.z) {
        case 0: src = x;  dst = g_xh;  break;
        case 1: src = wq; dst = g_wqh; break;
        case 2: src = wk; dst = g_wkh; break;
        case 3: src = wv; dst = g_wvh; break;
        default: src = wo; dst = g_woh; break;
    }
    size_t base = (size_t)blockIdx.x * 4096 + threadIdx.x * 4;
#pragma unroll
    for (int t = 0; t < 4; t++) {
        size_t e = base + t * 1024;
        float4 v = *(const float4*)&src[e];
        __half2 h0 = __floats2half2_rn(v.x, v.y);
        __half2 h1 = __floats2half2_rn(v.z, v.w);
        uint2 pk;
        pk.x = *(unsigned int*)&h0;
        pk.y = *(unsigned int*)&h1;
        *(uint2*)&dst[e] = pk;
    }
}

// ---------------------------------------------------------------------------
// GEMM: C[m,n] = sum_k A[m,k] * W[n,k]  (half inputs, fp32 accumulate/output)
// wmma m16n16k16. Block tile 128x128x64, 128 threads = 4 warps (2x2),
// each warp 64x64 = 4x4 fragments. 2-stage cp.async pipeline (proven).
// Smem 2 x 36864 = 73728 B  (INSIDE the proven <=81920 B envelope).
// KT = 64 k-tiles (barriers halved vs tf32/k32 version).
// mode 0: A = g_xh, C = {g_q,g_k,g_v}[z], W = {g_wqh,g_wkh,g_wvh}[z]
// mode 1: A = g_attnh, C = C_ext, W = g_woh
// ---------------------------------------------------------------------------
__global__ __launch_bounds__(128) void gemm_f16_kernel(float* __restrict__ C_ext,
                                                       int mode)
{
    constexpr int LDH = 72;                 // halfs per row: 64 + 8 pad (144 B)
    constexpr int STAGE = 128 * LDH * 2;    // halfs per stage (As + Bs)
    extern __shared__ __half smh[];         // 2 stages = 73728 bytes

    const int z = blockIdx.z;
    const __half* W = (mode == 0)
        ? ((z == 0) ? g_wqh : (z == 1) ? g_wkh : g_wvh) : g_woh;
    const __half* A = (mode == 0) ? g_xh : g_attnh;
    float* C = (mode == 0)
        ? ((z == 0) ? g_q : (z == 1) ? g_k : g_v) : C_ext;

    const int tid = threadIdx.x;
    const int m0 = blockIdx.y * 128;
    const int n0 = blockIdx.x * 128;
    const int warp = tid >> 5;       // 0..3
    const int wm = warp >> 1;        // 0..1 -> m offset wm*64
    const int wn = warp & 1;         // 0..1 -> n offset wn*64

    // Copy coords: 128 threads cover 16 rows x 8 chunks (8 halfs = 16 B each)
    const int cr = tid >> 3;          // 0..15
    const int cc = (tid & 7) << 3;    // 0,8,..,56 (halfs)

    wmma::fragment<wmma::accumulator, 16, 16, 16, float> acc[4][4];
#pragma unroll
    for (int i = 0; i < 4; i++)
#pragma unroll
        for (int j = 0; j < 4; j++)
            wmma::fill_fragment(acc[i][j], 0.0f);

    // Issue async copies of k-tile k0 (in halfs) into stage s
    auto issue = [&](int s, int k0) {
        __half* As = smh + s * STAGE;
        __half* Bs = As + 128 * LDH;
#pragma unroll
        for (int t = 0; t < 8; t++) {     // 8 rounds x 16 rows = 128 rows
            int r = cr + t * 16;
            unsigned int da =
                (unsigned int)__cvta_generic_to_shared(&As[r * LDH + cc]);
            cp_async16(da, &A[(size_t)(m0 + r) * ND + k0 + cc]);
            unsigned int db =
                (unsigned int)__cvta_generic_to_shared(&Bs[r * LDH + cc]);
            cp_async16(db, &W[(size_t)(n0 + r) * ND + k0 + cc]);
        }
        asm volatile("cp.async.commit_group;\n" ::);
    };

    issue(0, 0);
    int s = 0;
    constexpr int KT = ND / 64;  // 64 k-tiles

    for (int kt = 0; kt < KT; kt++) {
        if (kt + 1 < KT) {
            issue(s ^ 1, (kt + 1) * 64);
            asm volatile("cp.async.wait_group 1;\n" ::);
        } else {
            asm volatile("cp.async.wait_group 0;\n" ::);
        }
        __syncthreads();

        const __half* As = smh + s * STAGE;
        const __half* Bs = As + 128 * LDH;
#pragma unroll
        for (int kk = 0; kk < 64; kk += 16) {
            wmma::fragment<wmma::matrix_a, 16, 16, 16, __half,
                           wmma::row_major> af[4];
            wmma::fragment<wmma::matrix_b, 16, 16, 16, __half,
                           wmma::col_major> bf[4];
#pragma unroll
            for (int i = 0; i < 4; i++)
                wmma::load_matrix_sync(af[i], &As[(wm * 64 + i * 16) * LDH + kk], LDH);
#pragma unroll
            for (int j = 0; j < 4; j++)
                wmma::load_matrix_sync(bf[j], &Bs[(wn * 64 + j * 16) * LDH + kk], LDH);
#pragma unroll
            for (int i = 0; i < 4; i++)
#pragma unroll
                for (int j = 0; j < 4; j++)
                    wmma::mma_sync(acc[i][j], af[i], bf[j], acc[i][j]);
        }
        __syncthreads();   // all warps done reading stage s before refill
        s ^= 1;
    }

#pragma unroll
    for (int i = 0; i < 4; i++)
#pragma unroll
        for (int j = 0; j < 4; j++)
            wmma::store_matrix_sync(
                &C[(size_t)(m0 + wm * 64 + i * 16) * ND + n0 + wn * 64 + j * 16],
                acc[i][j], ND, wmma::mem_row_major);
}

// ---------------------------------------------------------------------------
// RoPE, in-place on g_q and g_k (fp32). One thread per (re,im) pair.
// ---------------------------------------------------------------------------
__global__ void rope_kernel(const float* __restrict__ fcos,
                            const float* __restrict__ fsin)
{
    int gid = blockIdx.x * blockDim.x + threadIdx.x;
    float* t = (gid < (1 << 23)) ? g_q : g_k;
    int p = gid & ((1 << 23) - 1);
    int row = p >> 11;           // 2048 pairs per row
    int pair = p & 2047;
    int i = pair & 63;           // pair index within head (HD/2 = 64)
    int s = row & 1023;          // sequence position
    float c = fcos[s * 64 + i];
    float sn = fsin[s * 64 + i];
    float2 v = *(float2*)&t[(size_t)row * ND + pair * 2];
    float2 o;
    o.x = v.x * c - v.y * sn;
    o.y = v.x * sn + v.y * c;
    *(float2*)&t[(size_t)row * ND + pair * 2] = o;
}

// ---------------------------------------------------------------------------
// Flash attention (online softmax), causal. Grid: (S/64, H, B). 256 threads
// as 16x16. fp32 math throughout; epilogue stores half into g_attnh (same
// 10-bit-mantissa rounding the old tf32 O-projection applied).
// ---------------------------------------------------------------------------
__global__ __launch_bounds__(256, 2) void attn_kernel()
{
    extern __shared__ float sma[];
    float* Qs = sma;                  // 64*128
    float* Ks = Qs + 64 * 128;        // 64*132 (pad 4 vs strided col reads)
    float* Vs = Ks + 64 * 132;        // 64*128
    float* Ps = Vs + 64 * 128;        // 64*64

    const int tid = threadIdx.x;
    const int ty = tid >> 4;
    const int tx = tid & 15;
    const int qt = blockIdx.x;
    const int h = blockIdx.y;
    const int b = blockIdx.z;
    const int q0 = qt * 64;

    const float scale = 0.08838834764831845f;  // 1/sqrt(128)
    const size_t base = (size_t)b * NS * ND + (size_t)h * NHD;

    // Load Q tile, pre-scaled
#pragma unroll
    for (int t = 0; t < 8; t++) {
        int e = tid + t * 256;
        int r = e >> 5;
        int c4 = (e & 31) << 2;
        float4 v = *(const float4*)&g_q[base + (size_t)(q0 + r) * ND + c4];
        v.x *= scale; v.y *= scale; v.z *= scale; v.w *= scale;
        *(float4*)&Qs[r * 128 + c4] = v;
    }

    float m_st[4], l_st[4], oacc[4][8];
#pragma unroll
    for (int i = 0; i < 4; i++) {
        m_st[i] = -1e30f;
        l_st[i] = 0.f;
#pragma unroll
        for (int c = 0; c < 8; c++) oacc[i][c] = 0.f;
    }

    for (int jt = 0; jt <= qt; jt++) {
        __syncthreads();  // protects Qs(first iter) & Ks/Vs/Ps from prior readers
#pragma unroll
        for (int t = 0; t < 8; t++) {
            int e = tid + t * 256;
            int r = e >> 5;
            int c4 = (e & 31) << 2;
            size_t g = base + (size_t)(jt * 64 + r) * ND + c4;
            *(float4*)&Ks[r * 132 + c4] = *(const float4*)&g_k[g];
            *(float4*)&Vs[r * 128 + c4] = *(const float4*)&g_v[g];
        }
        __syncthreads();

        // S = Qs * Ks^T   (4x4 per thread)
        float s[4][4];
#pragma unroll
        for (int i = 0; i < 4; i++)
#pragma unroll
            for (int j = 0; j < 4; j++) s[i][j] = 0.f;

        for (int d = 0; d < 128; d += 4) {
            float4 qv[4], kv[4];
#pragma unroll
            for (int i = 0; i < 4; i++)
                qv[i] = *(float4*)&Qs[(ty * 4 + i) * 128 + d];
#pragma unroll
            for (int j = 0; j < 4; j++)
                kv[j] = *(float4*)&Ks[(tx + 16 * j) * 132 + d];
#pragma unroll
            for (int i = 0; i < 4; i++)
#pragma unroll
                for (int j = 0; j < 4; j++)
                    s[i][j] += qv[i].x * kv[j].x + qv[i].y * kv[j].y +
                               qv[i].z * kv[j].z + qv[i].w * kv[j].w;
        }

        // Causal mask: only the diagonal tile needs elementwise masking
        if (jt == qt) {
#pragma unroll
            for (int i = 0; i < 4; i++)
#pragma unroll
                for (int j = 0; j < 4; j++)
                    if (tx + 16 * j > ty * 4 + i) s[i][j] = -1e30f;
        }

        // Online softmax (row reduce over tx = 16 lanes within each warp half)
#pragma unroll
        for (int i = 0; i < 4; i++) {
            float mx = fmaxf(fmaxf(s[i][0], s[i][1]), fmaxf(s[i][2], s[i][3]));
#pragma unroll
            for (int o = 8; o >= 1; o >>= 1)
                mx = fmaxf(mx, __shfl_xor_sync(0xffffffffu, mx, o));
            float mnew = fmaxf(m_st[i], mx);
            float alpha = __expf(m_st[i] - mnew);
            float rsum = 0.f;
#pragma unroll
            for (int j = 0; j < 4; j++) {
                float p = __expf(s[i][j] - mnew);
                Ps[(ty * 4 + i) * 64 + tx + 16 * j] = p;
                rsum += p;
            }
#pragma unroll
            for (int o = 8; o >= 1; o >>= 1)
                rsum += __shfl_xor_sync(0xffffffffu, rsum, o);
            l_st[i] = l_st[i] * alpha + rsum;
            m_st[i] = mnew;
#pragma unroll
            for (int c = 0; c < 8; c++) oacc[i][c] *= alpha;
        }
        __syncthreads();

        // O += P * V   (4 rows x 8 cols per thread)
        for (int kk = 0; kk < 64; kk++) {
            float pv[4];
#pragma unroll
            for (int i = 0; i < 4; i++) pv[i] = Ps[(ty * 4 + i) * 64 + kk];
            float4 v0 = *(float4*)&Vs[kk * 128 + tx * 8];
            float4 v1 = *(float4*)&Vs[kk * 128 + tx * 8 + 4];
#pragma unroll
            for (int i = 0; i < 4; i++) {
                oacc[i][0] += pv[i] * v0.x;
                oacc[i][1] += pv[i] * v0.y;
                oacc[i][2] += pv[i] * v0.z;
                oacc[i][3] += pv[i] * v0.w;
                oacc[i][4] += pv[i] * v1.x;
                oacc[i][5] += pv[i] * v1.y;
                oacc[i][6] += pv[i] * v1.z;
                oacc[i][7] += pv[i] * v1.w;
            }
        }
    }

    // Epilogue: normalize and write half into [B,S,H,HD] -> flat [B,S,D]
#pragma unroll
    for (int i = 0; i < 4; i++) {
        float inv = 1.f / l_st[i];
        __half2 h0 = __floats2half2_rn(oacc[i][0] * inv, oacc[i][1] * inv);
        __half2 h1 = __floats2half2_rn(oacc[i][2] * inv, oacc[i][3] * inv);
        __half2 h2 = __floats2half2_rn(oacc[i][4] * inv, oacc[i][5] * inv);
        __half2 h3 = __floats2half2_rn(oacc[i][6] * inv, oacc[i][7] * inv);
        uint4 pk;
        pk.x = *(unsigned int*)&h0;
        pk.y = *(unsigned int*)&h1;
        pk.z = *(unsigned int*)&h2;
        pk.w = *(unsigned int*)&h3;
        size_t g = base + (size_t)(q0 + ty * 4 + i) * ND + tx * 8;
        *(uint4*)&g_attnh[g] = pk;   // 16B store, tx*8 halfs -> 16B aligned
    }
}

// ---------------------------------------------------------------------------
extern "C" void kernel_launch(void* const* d_in, const int* in_sizes, int n_in,
                              void* d_out, int out_size)
{
    (void)in_sizes; (void)n_in; (void)out_size;
    const float* x    = (const float*)d_in[0];
    const float* wq   = (const float*)d_in[1];
    const float* wk   = (const float*)d_in[2];
    const float* wv   = (const float*)d_in[3];
    const float* wo   = (const float*)d_in[4];
    const float* fcos = (const float*)d_in[5];
    const float* fsin = (const float*)d_in[6];
    // d_in[7] = mask: causal tril, implemented directly in attn_kernel
    float* out = (float*)d_out;

    const int GEMM_SMEM = 2 * 128 * 72 * 2 * 2;  // 73728 B (2 stages, As+Bs, half)
    cudaFuncSetAttribute(gemm_f16_kernel,
                         cudaFuncAttributeMaxDynamicSharedMemorySize, GEMM_SMEM);

    const int ATT_SMEM = (64 * 128 + 64 * 132 + 64 * 128 + 64 * 64) * 4; // 115712
    cudaFuncSetAttribute(attn_kernel,
                         cudaFuncAttributeMaxDynamicSharedMemorySize, ATT_SMEM);

    // 0) fp32 -> fp16 pre-pass for x and all four weights
    f2h_kernel<<<dim3(4096, 1, 5), 256>>>(x, wq, wk, wv, wo);

    // 1) QKV projections (fused across grid.z), half in / fp32 out
    dim3 gqkv(32, 32, 3);
    gemm_f16_kernel<<<gqkv, 128, GEMM_SMEM>>>(nullptr, 0);

    // 2) RoPE on q and k (fp32 in-place; deterministic — GEMM rewrites scratch)
    rope_kernel<<<65536, 256>>>(fcos, fsin);

    // 3) Causal flash attention (fp32 math, half output)
    dim3 gatt(NS / 64, NH, NB);
    attn_kernel<<<gatt, 256, ATT_SMEM>>>();

    // 4) Output projection, half in / fp32 out
    dim3 go(32, 32, 1);
    gemm_f16_kernel<<<go, 128, GEMM_SMEM>>>(out, 1);
}

// round 16
// speedup vs baseline: 5.0223x; 1.3384x over previous
#include <cuda_runtime.h>
#include <cuda_fp16.h>
#include <cuda_bf16.h>
#include <mma.h>
#include <cstdint>

using namespace nvcuda;

// Problem shape (fixed): B=4, S=1024, D=4096, H=32, HD=128
#define NB 4
#define NS 1024
#define ND 4096
#define NH 32
#define NHD 128
#define NTOK (NB * NS)          // 4096 rows

// Scratch (device globals: the sanctioned no-alloc workaround).
__device__ float  g_q[(size_t)NTOK * ND];       // fp32 QKV outputs (rope in fp32)
__device__ float  g_k[(size_t)NTOK * ND];
__device__ float  g_v[(size_t)NTOK * ND];
__device__ __half g_xh[(size_t)NTOK * ND];      // half inputs for GEMMs
__device__ __half g_wqh[(size_t)ND * ND];
__device__ __half g_wkh[(size_t)ND * ND];
__device__ __half g_wvh[(size_t)ND * ND];
__device__ __half g_woh[(size_t)ND * ND];
__device__ __half g_attnh[(size_t)NTOK * ND];   // attention output (half)

__device__ __forceinline__ void cp_async16(unsigned int dst, const void* src) {
    asm volatile("cp.async.cg.shared.global [%0], [%1], 16;\n" ::"r"(dst), "l"(src));
}

// ---------------------------------------------------------------------------
// fp32 -> fp16 convert pre-pass. grid = (4096, 1, 5).
// ---------------------------------------------------------------------------
__global__ void f2h_kernel(const float* __restrict__ x,
                           const float* __restrict__ wq,
                           const float* __restrict__ wk,
                           const float* __restrict__ wv,
                           const float* __restrict__ wo)
{
    const float* src;
    __half* dst;
    switch (blockIdx.z) {
        case 0: src = x;  dst = g_xh;  break;
        case 1: src = wq; dst = g_wqh; break;
        case 2: src = wk; dst = g_wkh; break;
        case 3: src = wv; dst = g_wvh; break;
        default: src = wo; dst = g_woh; break;
    }
    size_t base = (size_t)blockIdx.x * 4096 + threadIdx.x * 4;
#pragma unroll
    for (int t = 0; t < 4; t++) {
        size_t e = base + t * 1024;
        float4 v = *(const float4*)&src[e];
        __half2 h0 = __floats2half2_rn(v.x, v.y);
        __half2 h1 = __floats2half2_rn(v.z, v.w);
        uint2 pk;
        pk.x = *(unsigned int*)&h0;
        pk.y = *(unsigned int*)&h1;
        *(uint2*)&dst[e] = pk;
    }
}

// ---------------------------------------------------------------------------
// GEMM (unchanged from R15 passing version): half in / fp32 out, m16n16k16,
// block 128x128x64, 4 warps x 64x64 frags, 2-stage cp.async, 73728 B smem.
// ---------------------------------------------------------------------------
__global__ __launch_bounds__(128) void gemm_f16_kernel(float* __restrict__ C_ext,
                                                       int mode)
{
    constexpr int LDH = 72;
    constexpr int STAGE = 128 * LDH * 2;
    extern __shared__ __half smh[];

    const int z = blockIdx.z;
    const __half* W = (mode == 0)
        ? ((z == 0) ? g_wqh : (z == 1) ? g_wkh : g_wvh) : g_woh;
    const __half* A = (mode == 0) ? g_xh : g_attnh;
    float* C = (mode == 0)
        ? ((z == 0) ? g_q : (z == 1) ? g_k : g_v) : C_ext;

    const int tid = threadIdx.x;
    const int m0 = blockIdx.y * 128;
    const int n0 = blockIdx.x * 128;
    const int warp = tid >> 5;
    const int wm = warp >> 1;
    const int wn = warp & 1;

    const int cr = tid >> 3;
    const int cc = (tid & 7) << 3;

    wmma::fragment<wmma::accumulator, 16, 16, 16, float> acc[4][4];
#pragma unroll
    for (int i = 0; i < 4; i++)
#pragma unroll
        for (int j = 0; j < 4; j++)
            wmma::fill_fragment(acc[i][j], 0.0f);

    auto issue = [&](int s, int k0) {
        __half* As = smh + s * STAGE;
        __half* Bs = As + 128 * LDH;
#pragma unroll
        for (int t = 0; t < 8; t++) {
            int r = cr + t * 16;
            unsigned int da =
                (unsigned int)__cvta_generic_to_shared(&As[r * LDH + cc]);
            cp_async16(da, &A[(size_t)(m0 + r) * ND + k0 + cc]);
            unsigned int db =
                (unsigned int)__cvta_generic_to_shared(&Bs[r * LDH + cc]);
            cp_async16(db, &W[(size_t)(n0 + r) * ND + k0 + cc]);
        }
        asm volatile("cp.async.commit_group;\n" ::);
    };

    issue(0, 0);
    int s = 0;
    constexpr int KT = ND / 64;

    for (int kt = 0; kt < KT; kt++) {
        if (kt + 1 < KT) {
            issue(s ^ 1, (kt + 1) * 64);
            asm volatile("cp.async.wait_group 1;\n" ::);
        } else {
            asm volatile("cp.async.wait_group 0;\n" ::);
        }
        __syncthreads();

        const __half* As = smh + s * STAGE;
        const __half* Bs = As + 128 * LDH;
#pragma unroll
        for (int kk = 0; kk < 64; kk += 16) {
            wmma::fragment<wmma::matrix_a, 16, 16, 16, __half,
                           wmma::row_major> af[4];
            wmma::fragment<wmma::matrix_b, 16, 16, 16, __half,
                           wmma::col_major> bf[4];
#pragma unroll
            for (int i = 0; i < 4; i++)
                wmma::load_matrix_sync(af[i], &As[(wm * 64 + i * 16) * LDH + kk], LDH);
#pragma unroll
            for (int j = 0; j < 4; j++)
                wmma::load_matrix_sync(bf[j], &Bs[(wn * 64 + j * 16) * LDH + kk], LDH);
#pragma unroll
            for (int i = 0; i < 4; i++)
#pragma unroll
                for (int j = 0; j < 4; j++)
                    wmma::mma_sync(acc[i][j], af[i], bf[j], acc[i][j]);
        }
        __syncthreads();
        s ^= 1;
    }

#pragma unroll
    for (int i = 0; i < 4; i++)
#pragma unroll
        for (int j = 0; j < 4; j++)
            wmma::store_matrix_sync(
                &C[(size_t)(m0 + wm * 64 + i * 16) * ND + n0 + wn * 64 + j * 16],
                acc[i][j], ND, wmma::mem_row_major);
}

// ---------------------------------------------------------------------------
// RoPE, in-place on g_q and g_k (fp32). One thread per (re,im) pair.
// ---------------------------------------------------------------------------
__global__ void rope_kernel(const float* __restrict__ fcos,
                            const float* __restrict__ fsin)
{
    int gid = blockIdx.x * blockDim.x + threadIdx.x;
    float* t = (gid < (1 << 23)) ? g_q : g_k;
    int p = gid & ((1 << 23) - 1);
    int row = p >> 11;
    int pair = p & 2047;
    int i = pair & 63;
    int s = row & 1023;
    float c = fcos[s * 64 + i];
    float sn = fsin[s * 64 + i];
    float2 v = *(float2*)&t[(size_t)row * ND + pair * 2];
    float2 o;
    o.x = v.x * c - v.y * sn;
    o.y = v.x * sn + v.y * c;
    *(float2*)&t[(size_t)row * ND + pair * 2] = o;
}

// ---------------------------------------------------------------------------
// Tensor-core flash attention (online softmax), causal.
// Grid (S/64, H, B), 256 threads = 8 warps.
// S = Q*K^T and O += P*V on fp16 wmma (fp32 accum). All fragments round-trip
// through smem so layouts are explicit; O accumulator lives in smem fp32 and
// is rescaled there (no opaque-fragment rescale).
// Smem: Qh/Kh/Vh 64x136 half, Ph 64x72 half, Ss 64x68 f32, Os 64x132 f32
//     = 112640 B (inside proven <=115712 envelope).
// ---------------------------------------------------------------------------
__global__ __launch_bounds__(256) void attn_kernel()
{
    extern __shared__ char smraw[];
    __half* Qh = (__half*)smraw;            // 64*136
    __half* Kh = Qh + 64 * 136;             // 64*136
    __half* Vh = Kh + 64 * 136;             // 64*136
    __half* Ph = Vh + 64 * 136;             // 64*72
    float*  Ss = (float*)(Ph + 64 * 72);    // 64*68
    float*  Os = Ss + 64 * 68;              // 64*132

    const int tid = threadIdx.x;
    const int warp = tid >> 5;
    const int qt = blockIdx.x;
    const int h = blockIdx.y;
    const int b = blockIdx.z;
    const int q0 = qt * 64;

    const float scale = 0.08838834764831845f;  // 1/sqrt(128)
    const size_t base = (size_t)b * NS * ND + (size_t)h * NHD;

    // Load Q tile (scaled, fp32 -> half)
#pragma unroll
    for (int t = 0; t < 8; t++) {
        int e = tid + t * 256;            // 2048 float4-chunks = 64 x 128
        int r = e >> 5;
        int c4 = (e & 31) << 2;
        float4 v = *(const float4*)&g_q[base + (size_t)(q0 + r) * ND + c4];
        __half2 h0 = __floats2half2_rn(v.x * scale, v.y * scale);
        __half2 h1 = __floats2half2_rn(v.z * scale, v.w * scale);
        uint2 pk;
        pk.x = *(unsigned int*)&h0;
        pk.y = *(unsigned int*)&h1;
        *(uint2*)&Qh[r * 136 + c4] = pk;
    }
    // Zero O accumulator (64 x 128 region of 64 x 132 buffer)
#pragma unroll
    for (int t = 0; t < 33; t++) {
        int e = tid + t * 256;            // 8448 = 64*132
        if (e < 64 * 132) Os[e] = 0.0f;
    }

    // Per-row softmax state: thread t owns row (t>>2); 4 threads per row.
    const int srow = tid >> 2;
    const int sgrp = tid & 3;
    float m_st = -1e30f, l_st = 0.0f;

    for (int jt = 0; jt <= qt; jt++) {
        __syncthreads();   // prev PV done (Vh/Ph/Os quiesced); Q/Os init visible
        // Load K and V tiles (fp32 -> half)
#pragma unroll
        for (int t = 0; t < 8; t++) {
            int e = tid + t * 256;
            int r = e >> 5;
            int c4 = (e & 31) << 2;
            size_t g = base + (size_t)(jt * 64 + r) * ND + c4;
            float4 kv = *(const float4*)&g_k[g];
            float4 vv = *(const float4*)&g_v[g];
            __half2 k0 = __floats2half2_rn(kv.x, kv.y);
            __half2 k1 = __floats2half2_rn(kv.z, kv.w);
            __half2 v0 = __floats2half2_rn(vv.x, vv.y);
            __half2 v1 = __floats2half2_rn(vv.z, vv.w);
            uint2 pk, pv;
            pk.x = *(unsigned int*)&k0; pk.y = *(unsigned int*)&k1;
            pv.x = *(unsigned int*)&v0; pv.y = *(unsigned int*)&v1;
            *(uint2*)&Kh[r * 136 + c4] = pk;
            *(uint2*)&Vh[r * 136 + c4] = pv;
        }
        __syncthreads();

        // S = Q * K^T : warp w -> rows (w>>1)*16, cols (w&1)*32 (2 tiles)
        {
            const int r0 = (warp >> 1) * 16;
            const int c0 = (warp & 1) * 32;
            wmma::fragment<wmma::accumulator, 16, 16, 16, float> sacc[2];
            wmma::fill_fragment(sacc[0], 0.0f);
            wmma::fill_fragment(sacc[1], 0.0f);
#pragma unroll
            for (int kk = 0; kk < 128; kk += 16) {
                wmma::fragment<wmma::matrix_a, 16, 16, 16, __half,
                               wmma::row_major> aq;
                wmma::load_matrix_sync(aq, &Qh[r0 * 136 + kk], 136);
#pragma unroll
                for (int j = 0; j < 2; j++) {
                    wmma::fragment<wmma::matrix_b, 16, 16, 16, __half,
                                   wmma::col_major> bk;
                    wmma::load_matrix_sync(bk, &Kh[(c0 + j * 16) * 136 + kk], 136);
                    wmma::mma_sync(sacc[j], aq, bk, sacc[j]);
                }
            }
#pragma unroll
            for (int j = 0; j < 2; j++)
                wmma::store_matrix_sync(&Ss[r0 * 68 + c0 + j * 16], sacc[j],
                                        68, wmma::mem_row_major);
        }
        __syncthreads();

        // Online softmax: thread owns row srow, cols sgrp*16..+16
        {
            float sv[16];
            const int cbase = sgrp * 16;
            const bool diag = (jt == qt);
#pragma unroll
            for (int i = 0; i < 16; i++) {
                float x = Ss[srow * 68 + cbase + i];
                if (diag && (cbase + i > srow)) x = -1e30f;
                sv[i] = x;
            }
            float mx = sv[0];
#pragma unroll
            for (int i = 1; i < 16; i++) mx = fmaxf(mx, sv[i]);
            mx = fmaxf(mx, __shfl_xor_sync(0xffffffffu, mx, 1));
            mx = fmaxf(mx, __shfl_xor_sync(0xffffffffu, mx, 2));
            float mnew = fmaxf(m_st, mx);
            float alpha = __expf(m_st - mnew);
            float rsum = 0.0f;
#pragma unroll
            for (int i = 0; i < 16; i += 2) {
                float p0 = __expf(sv[i] - mnew);
                float p1 = __expf(sv[i + 1] - mnew);
                rsum += p0 + p1;
                __half2 hp = __floats2half2_rn(p0, p1);
                *(unsigned int*)&Ph[srow * 72 + cbase + i] = *(unsigned int*)&hp;
            }
            rsum += __shfl_xor_sync(0xffffffffu, rsum, 1);
            rsum += __shfl_xor_sync(0xffffffffu, rsum, 2);
            l_st = l_st * alpha + rsum;
            m_st = mnew;
            // Rescale O row: this thread handles cols sgrp*32..+32
            const int ob = srow * 132 + sgrp * 32;
#pragma unroll
            for (int i = 0; i < 32; i++) Os[ob + i] *= alpha;
        }
        __syncthreads();

        // O += P * V : warp w -> rows (w>>1)*16, cols (w&1)*64 (4 tiles)
        {
            const int r0 = (warp >> 1) * 16;
            const int c0 = (warp & 1) * 64;
            wmma::fragment<wmma::accumulator, 16, 16, 16, float> oacc[4];
#pragma unroll
            for (int j = 0; j < 4; j++)
                wmma::load_matrix_sync(oacc[j], &Os[r0 * 132 + c0 + j * 16],
                                       132, wmma::mem_row_major);
#pragma unroll
            for (int kk = 0; kk < 64; kk += 16) {
                wmma::fragment<wmma::matrix_a, 16, 16, 16, __half,
                               wmma::row_major> ap;
                wmma::load_matrix_sync(ap, &Ph[r0 * 72 + kk], 72);
#pragma unroll
                for (int j = 0; j < 4; j++) {
                    wmma::fragment<wmma::matrix_b, 16, 16, 16, __half,
                                   wmma::row_major> bv;
                    wmma::load_matrix_sync(bv, &Vh[kk * 136 + c0 + j * 16], 136);
                    wmma::mma_sync(oacc[j], ap, bv, oacc[j]);
                }
            }
#pragma unroll
            for (int j = 0; j < 4; j++)
                wmma::store_matrix_sync(&Os[r0 * 132 + c0 + j * 16], oacc[j],
                                        132, wmma::mem_row_major);
        }
    }
    __syncthreads();

    // Epilogue: row srow, cols sgrp*32..+32 -> g_attnh (half)
    {
        float inv = 1.0f / l_st;
        const int cb = sgrp * 32;
        size_t g = base + (size_t)(q0 + srow) * ND + cb;
#pragma unroll
        for (int c8 = 0; c8 < 32; c8 += 8) {
            uint4 pk;
            __half2 h0 = __floats2half2_rn(Os[srow * 132 + cb + c8 + 0] * inv,
                                           Os[srow * 132 + cb + c8 + 1] * inv);
            __half2 h1 = __floats2half2_rn(Os[srow * 132 + cb + c8 + 2] * inv,
                                           Os[srow * 132 + cb + c8 + 3] * inv);
            __half2 h2 = __floats2half2_rn(Os[srow * 132 + cb + c8 + 4] * inv,
                                           Os[srow * 132 + cb + c8 + 5] * inv);
            __half2 h3 = __floats2half2_rn(Os[srow * 132 + cb + c8 + 6] * inv,
                                           Os[srow * 132 + cb + c8 + 7] * inv);
            pk.x = *(unsigned int*)&h0;
            pk.y = *(unsigned int*)&h1;
            pk.z = *(unsigned int*)&h2;
            pk.w = *(unsigned int*)&h3;
            *(uint4*)&g_attnh[g + c8] = pk;
        }
    }
}

// ---------------------------------------------------------------------------
extern "C" void kernel_launch(void* const* d_in, const int* in_sizes, int n_in,
                              void* d_out, int out_size)
{
    (void)in_sizes; (void)n_in; (void)out_size;
    const float* x    = (const float*)d_in[0];
    const float* wq   = (const float*)d_in[1];
    const float* wk   = (const float*)d_in[2];
    const float* wv   = (const float*)d_in[3];
    const float* wo   = (const float*)d_in[4];
    const float* fcos = (const float*)d_in[5];
    const float* fsin = (const float*)d_in[6];
    // d_in[7] = mask: causal tril, implemented directly in attn_kernel
    float* out = (float*)d_out;

    const int GEMM_SMEM = 2 * 128 * 72 * 2 * 2;  // 73728 B
    cudaFuncSetAttribute(gemm_f16_kernel,
                         cudaFuncAttributeMaxDynamicSharedMemorySize, GEMM_SMEM);

    const int ATT_SMEM = (3 * 64 * 136 + 64 * 72) * 2 + (64 * 68 + 64 * 132) * 4;
    // = 112640 B
    cudaFuncSetAttribute(attn_kernel,
                         cudaFuncAttributeMaxDynamicSharedMemorySize, ATT_SMEM);

    // 0) fp32 -> fp16 pre-pass for x and all four weights
    f2h_kernel<<<dim3(4096, 1, 5), 256>>>(x, wq, wk, wv, wo);

    // 1) QKV projections (fused across grid.z), half in / fp32 out
    dim3 gqkv(32, 32, 3);
    gemm_f16_kernel<<<gqkv, 128, GEMM_SMEM>>>(nullptr, 0);

    // 2) RoPE on q and k (fp32 in-place)
    rope_kernel<<<65536, 256>>>(fcos, fsin);

    // 3) Causal flash attention (tensor-core QK^T and PV)
    dim3 gatt(NS / 64, NH, NB);
    attn_kernel<<<gatt, 256, ATT_SMEM>>>();

    // 4) Output projection, half in / fp32 out
    dim3 go(32, 32, 1);
    gemm_f16_kernel<<<go, 128, GEMM_SMEM>>>(out, 1);
}

// round 17
// speedup vs baseline: 5.5132x; 1.0977x over previous
#include <cuda_runtime.h>
#include <cuda_fp16.h>
#include <cuda_bf16.h>
#include <mma.h>
#include <cstdint>

using namespace nvcuda;

// Problem shape (fixed): B=4, S=1024, D=4096, H=32, HD=128
#define NB 4
#define NS 1024
#define ND 4096
#define NH 32
#define NHD 128
#define NTOK (NB * NS)          // 4096 rows

// Scratch (device globals: the sanctioned no-alloc workaround).
__device__ float  g_q[(size_t)NTOK * ND];       // fp32 QKV outputs (rope in fp32)
__device__ float  g_k[(size_t)NTOK * ND];
__device__ float  g_v[(size_t)NTOK * ND];
__device__ __half g_xh[(size_t)NTOK * ND];      // half inputs for GEMMs
__device__ __half g_wqh[(size_t)ND * ND];
__device__ __half g_wkh[(size_t)ND * ND];
__device__ __half g_wvh[(size_t)ND * ND];
__device__ __half g_woh[(size_t)ND * ND];
__device__ __half g_attnh[(size_t)NTOK * ND];   // attention output (half)

__device__ __forceinline__ void cp_async16(unsigned int dst, const void* src) {
    asm volatile("cp.async.cg.shared.global [%0], [%1], 16;\n" ::"r"(dst), "l"(src));
}

// mma.sync m16n8k16 row.col f32 += f16*f16, accumulate in place.
__device__ __forceinline__ void mma16816(float* c, const unsigned* a,
                                         const unsigned* b) {
    asm volatile(
        "mma.sync.aligned.m16n8k16.row.col.f32.f16.f16.f32 "
        "{%0,%1,%2,%3}, {%4,%5,%6,%7}, {%8,%9}, {%0,%1,%2,%3};\n"
        : "+f"(c[0]), "+f"(c[1]), "+f"(c[2]), "+f"(c[3])
        : "r"(a[0]), "r"(a[1]), "r"(a[2]), "r"(a[3]), "r"(b[0]), "r"(b[1]));
}

// ---------------------------------------------------------------------------
// fp32 -> fp16 convert pre-pass. grid = (4096, 1, 5).  (unchanged)
// ---------------------------------------------------------------------------
__global__ void f2h_kernel(const float* __restrict__ x,
                           const float* __restrict__ wq,
                           const float* __restrict__ wk,
                           const float* __restrict__ wv,
                           const float* __restrict__ wo)
{
    const float* src;
    __half* dst;
    switch (blockIdx.z) {
        case 0: src = x;  dst = g_xh;  break;
        case 1: src = wq; dst = g_wqh; break;
        case 2: src = wk; dst = g_wkh; break;
        case 3: src = wv; dst = g_wvh; break;
        default: src = wo; dst = g_woh; break;
    }
    size_t base = (size_t)blockIdx.x * 4096 + threadIdx.x * 4;
#pragma unroll
    for (int t = 0; t < 4; t++) {
        size_t e = base + t * 1024;
        float4 v = *(const float4*)&src[e];
        __half2 h0 = __floats2half2_rn(v.x, v.y);
        __half2 h1 = __floats2half2_rn(v.z, v.w);
        uint2 pk;
        pk.x = *(unsigned int*)&h0;
        pk.y = *(unsigned int*)&h1;
        *(uint2*)&dst[e] = pk;
    }
}

// ---------------------------------------------------------------------------
// GEMM (unchanged passing version): half in / fp32 out, m16n16k16,
// block 128x128x64, 4 warps x 64x64 frags, 2-stage cp.async, 73728 B smem.
// ---------------------------------------------------------------------------
__global__ __launch_bounds__(128) void gemm_f16_kernel(float* __restrict__ C_ext,
                                                       int mode)
{
    constexpr int LDH = 72;
    constexpr int STAGE = 128 * LDH * 2;
    extern __shared__ __half smh[];

    const int z = blockIdx.z;
    const __half* W = (mode == 0)
        ? ((z == 0) ? g_wqh : (z == 1) ? g_wkh : g_wvh) : g_woh;
    const __half* A = (mode == 0) ? g_xh : g_attnh;
    float* C = (mode == 0)
        ? ((z == 0) ? g_q : (z == 1) ? g_k : g_v) : C_ext;

    const int tid = threadIdx.x;
    const int m0 = blockIdx.y * 128;
    const int n0 = blockIdx.x * 128;
    const int warp = tid >> 5;
    const int wm = warp >> 1;
    const int wn = warp & 1;

    const int cr = tid >> 3;
    const int cc = (tid & 7) << 3;

    wmma::fragment<wmma::accumulator, 16, 16, 16, float> acc[4][4];
#pragma unroll
    for (int i = 0; i < 4; i++)
#pragma unroll
        for (int j = 0; j < 4; j++)
            wmma::fill_fragment(acc[i][j], 0.0f);

    auto issue = [&](int s, int k0) {
        __half* As = smh + s * STAGE;
        __half* Bs = As + 128 * LDH;
#pragma unroll
        for (int t = 0; t < 8; t++) {
            int r = cr + t * 16;
            unsigned int da =
                (unsigned int)__cvta_generic_to_shared(&As[r * LDH + cc]);
            cp_async16(da, &A[(size_t)(m0 + r) * ND + k0 + cc]);
            unsigned int db =
                (unsigned int)__cvta_generic_to_shared(&Bs[r * LDH + cc]);
            cp_async16(db, &W[(size_t)(n0 + r) * ND + k0 + cc]);
        }
        asm volatile("cp.async.commit_group;\n" ::);
    };

    issue(0, 0);
    int s = 0;
    constexpr int KT = ND / 64;

    for (int kt = 0; kt < KT; kt++) {
        if (kt + 1 < KT) {
            issue(s ^ 1, (kt + 1) * 64);
            asm volatile("cp.async.wait_group 1;\n" ::);
        } else {
            asm volatile("cp.async.wait_group 0;\n" ::);
        }
        __syncthreads();

        const __half* As = smh + s * STAGE;
        const __half* Bs = As + 128 * LDH;
#pragma unroll
        for (int kk = 0; kk < 64; kk += 16) {
            wmma::fragment<wmma::matrix_a, 16, 16, 16, __half,
                           wmma::row_major> af[4];
            wmma::fragment<wmma::matrix_b, 16, 16, 16, __half,
                           wmma::col_major> bf[4];
#pragma unroll
            for (int i = 0; i < 4; i++)
                wmma::load_matrix_sync(af[i], &As[(wm * 64 + i * 16) * LDH + kk], LDH);
#pragma unroll
            for (int j = 0; j < 4; j++)
                wmma::load_matrix_sync(bf[j], &Bs[(wn * 64 + j * 16) * LDH + kk], LDH);
#pragma unroll
            for (int i = 0; i < 4; i++)
#pragma unroll
                for (int j = 0; j < 4; j++)
                    wmma::mma_sync(acc[i][j], af[i], bf[j], acc[i][j]);
        }
        __syncthreads();
        s ^= 1;
    }

#pragma unroll
    for (int i = 0; i < 4; i++)
#pragma unroll
        for (int j = 0; j < 4; j++)
            wmma::store_matrix_sync(
                &C[(size_t)(m0 + wm * 64 + i * 16) * ND + n0 + wn * 64 + j * 16],
                acc[i][j], ND, wmma::mem_row_major);
}

// ---------------------------------------------------------------------------
// RoPE, in-place on g_q and g_k (fp32). One thread per (re,im) pair. (unchanged)
// ---------------------------------------------------------------------------
__global__ void rope_kernel(const float* __restrict__ fcos,
                            const float* __restrict__ fsin)
{
    int gid = blockIdx.x * blockDim.x + threadIdx.x;
    float* t = (gid < (1 << 23)) ? g_q : g_k;
    int p = gid & ((1 << 23) - 1);
    int row = p >> 11;
    int pair = p & 2047;
    int i = pair & 63;
    int s = row & 1023;
    float c = fcos[s * 64 + i];
    float sn = fsin[s * 64 + i];
    float2 v = *(float2*)&t[(size_t)row * ND + pair * 2];
    float2 o;
    o.x = v.x * c - v.y * sn;
    o.y = v.x * sn + v.y * c;
    *(float2*)&t[(size_t)row * ND + pair * 2] = o;
}

// ---------------------------------------------------------------------------
// FA2-style flash attention with raw mma.sync.m16n8k16 (documented layouts).
// Grid (S/64, H, B), 128 threads = 4 warps; warp w owns query rows w*16..+16.
// Register-resident: Q (A-frags, loaded once), S/P (C->A identity), O (C-frags,
// per-row rescale is a register multiply since thread owns rows lane>>2, +8).
// Smem only K (k-major 64x136) and V (transposed 128x72) = 35840 B.
// ---------------------------------------------------------------------------
__global__ __launch_bounds__(128) void attn_kernel()
{
    extern __shared__ __half smha[];
    __half* Kh = smha;             // 64 rows (key) x 136 cols (headdim+pad)
    __half* Vt = Kh + 64 * 136;    // 128 rows (headdim) x 72 cols (key+pad)

    const int tid = threadIdx.x;
    const int warp = tid >> 5;
    const int lane = tid & 31;
    const int lr = lane >> 2;      // fragment row within 0..7
    const int mq = lane & 3;       // fragment col group
    const int wbase = warp * 16;   // query-row base of this warp

    const int qt = blockIdx.x;
    const int h = blockIdx.y;
    const int b = blockIdx.z;
    const int q0 = qt * 64;

    const float scale = 0.08838834764831845f;  // 1/sqrt(128)
    const size_t base = (size_t)b * NS * ND + (size_t)h * NHD;

    // ---- Stage Q (scaled fp32 -> half) into Kh, then extract A-fragments ----
#pragma unroll
    for (int t = 0; t < 16; t++) {
        int e = tid + t * 128;            // 2048 float4 cells = 64 x 32
        int r = e >> 5;
        int c4 = (e & 31) << 2;
        float4 v = *(const float4*)&g_q[base + (size_t)(q0 + r) * ND + c4];
        __half2 h0 = __floats2half2_rn(v.x * scale, v.y * scale);
        __half2 h1 = __floats2half2_rn(v.z * scale, v.w * scale);
        uint2 pk;
        pk.x = *(unsigned int*)&h0;
        pk.y = *(unsigned int*)&h1;
        *(uint2*)&Kh[r * 136 + c4] = pk;
    }
    __syncthreads();

    // Q A-fragments: qa[kt][4], kt over 8 k16-chunks of headdim 128.
    unsigned qa[8][4];
#pragma unroll
    for (int kt = 0; kt < 8; kt++) {
        int cb = kt * 16 + 2 * mq;
        qa[kt][0] = *(unsigned*)&Kh[(wbase + lr) * 136 + cb];
        qa[kt][1] = *(unsigned*)&Kh[(wbase + lr + 8) * 136 + cb];
        qa[kt][2] = *(unsigned*)&Kh[(wbase + lr) * 136 + cb + 8];
        qa[kt][3] = *(unsigned*)&Kh[(wbase + lr + 8) * 136 + cb + 8];
    }

    // O accumulator: 16 n8-tiles covering headdim 128. Softmax state for the
    // two rows this thread owns (wbase+lr, wbase+lr+8).
    float oc[16][4];
#pragma unroll
    for (int j = 0; j < 16; j++) {
        oc[j][0] = 0.f; oc[j][1] = 0.f; oc[j][2] = 0.f; oc[j][3] = 0.f;
    }
    float m0 = -1e30f, m1 = -1e30f, l0 = 0.f, l1 = 0.f;

    const int grow0 = q0 + wbase + lr;
    const int grow1 = grow0 + 8;

    for (int jt = 0; jt <= qt; jt++) {
        __syncthreads();   // Q-extract done (1st iter) / prev PV LDS done
        // Load K tile (k-major) and V tile (transposed) fp32 -> half
#pragma unroll
        for (int t = 0; t < 16; t++) {
            int e = tid + t * 128;
            int r = e >> 5;
            int c4 = (e & 31) << 2;
            float4 kv = *(const float4*)&g_k[base + (size_t)(jt * 64 + r) * ND + c4];
            __half2 k0 = __floats2half2_rn(kv.x, kv.y);
            __half2 k1 = __floats2half2_rn(kv.z, kv.w);
            uint2 pk;
            pk.x = *(unsigned int*)&k0;
            pk.y = *(unsigned int*)&k1;
            *(uint2*)&Kh[r * 136 + c4] = pk;
        }
#pragma unroll
        for (int t = 0; t < 8; t++) {
            int e = tid + t * 128;        // 1024 cells = 32 k-pairs x 32 d-quads
            int k2 = e >> 5;              // key pair index 0..31
            int d4 = e & 31;              // headdim quad 0..31
            size_t g0 = base + (size_t)(jt * 64 + 2 * k2) * ND + 4 * d4;
            float4 va = *(const float4*)&g_v[g0];
            float4 vb = *(const float4*)&g_v[g0 + ND];
            __half2 p0 = __floats2half2_rn(va.x, vb.x);
            __half2 p1 = __floats2half2_rn(va.y, vb.y);
            __half2 p2 = __floats2half2_rn(va.z, vb.z);
            __half2 p3 = __floats2half2_rn(va.w, vb.w);
            *(unsigned*)&Vt[(4 * d4 + 0) * 72 + 2 * k2] = *(unsigned*)&p0;
            *(unsigned*)&Vt[(4 * d4 + 1) * 72 + 2 * k2] = *(unsigned*)&p1;
            *(unsigned*)&Vt[(4 * d4 + 2) * 72 + 2 * k2] = *(unsigned*)&p2;
            *(unsigned*)&Vt[(4 * d4 + 3) * 72 + 2 * k2] = *(unsigned*)&p3;
        }
        __syncthreads();

        // ---- S = Q * K^T : 8 n8-tiles (64 keys), accumulate over 8 k-chunks
        float sc[8][4];
#pragma unroll
        for (int j = 0; j < 8; j++) {
            sc[j][0] = 0.f; sc[j][1] = 0.f; sc[j][2] = 0.f; sc[j][3] = 0.f;
        }
#pragma unroll
        for (int jn = 0; jn < 8; jn++) {
            const __half* kr = &Kh[(jn * 8 + lr) * 136];
#pragma unroll
            for (int kt = 0; kt < 8; kt++) {
                unsigned bb[2];
                bb[0] = *(unsigned*)&kr[kt * 16 + 2 * mq];
                bb[1] = *(unsigned*)&kr[kt * 16 + 2 * mq + 8];
                mma16816(sc[jn], qa[kt], bb);
            }
        }

        // ---- Online softmax on register S (rows grow0, grow1) ----
        const bool diag = (jt == qt);
        float mx0 = -1e30f, mx1 = -1e30f;
#pragma unroll
        for (int j = 0; j < 8; j++) {
            int c0 = jt * 64 + j * 8 + 2 * mq;
            if (diag) {
                if (c0     > grow0) sc[j][0] = -1e30f;
                if (c0 + 1 > grow0) sc[j][1] = -1e30f;
                if (c0     > grow1) sc[j][2] = -1e30f;
                if (c0 + 1 > grow1) sc[j][3] = -1e30f;
            }
            mx0 = fmaxf(mx0, fmaxf(sc[j][0], sc[j][1]));
            mx1 = fmaxf(mx1, fmaxf(sc[j][2], sc[j][3]));
        }
        mx0 = fmaxf(mx0, __shfl_xor_sync(0xffffffffu, mx0, 1));
        mx0 = fmaxf(mx0, __shfl_xor_sync(0xffffffffu, mx0, 2));
        mx1 = fmaxf(mx1, __shfl_xor_sync(0xffffffffu, mx1, 1));
        mx1 = fmaxf(mx1, __shfl_xor_sync(0xffffffffu, mx1, 2));
        float mn0 = fmaxf(m0, mx0), mn1 = fmaxf(m1, mx1);
        float al0 = __expf(m0 - mn0), al1 = __expf(m1 - mn1);
        float rs0 = 0.f, rs1 = 0.f;
        unsigned pa[4][4];   // P as A-fragments (C->A layout identity)
#pragma unroll
        for (int kt = 0; kt < 4; kt++) {
#pragma unroll
            for (int jj = 0; jj < 2; jj++) {
                int j = 2 * kt + jj;
                float e0 = __expf(sc[j][0] - mn0);
                float e1 = __expf(sc[j][1] - mn0);
                float e2 = __expf(sc[j][2] - mn1);
                float e3 = __expf(sc[j][3] - mn1);
                rs0 += e0 + e1;
                rs1 += e2 + e3;
                __half2 hA = __floats2half2_rn(e0, e1);
                __half2 hB = __floats2half2_rn(e2, e3);
                pa[kt][jj * 2]     = *(unsigned*)&hA;
                pa[kt][jj * 2 + 1] = *(unsigned*)&hB;
            }
        }
        rs0 += __shfl_xor_sync(0xffffffffu, rs0, 1);
        rs0 += __shfl_xor_sync(0xffffffffu, rs0, 2);
        rs1 += __shfl_xor_sync(0xffffffffu, rs1, 1);
        rs1 += __shfl_xor_sync(0xffffffffu, rs1, 2);
        l0 = l0 * al0 + rs0;
        l1 = l1 * al1 + rs1;
        m0 = mn0;
        m1 = mn1;

        // Rescale O in registers (thread owns rows grow0, grow1)
#pragma unroll
        for (int j = 0; j < 16; j++) {
            oc[j][0] *= al0; oc[j][1] *= al0;
            oc[j][2] *= al1; oc[j][3] *= al1;
        }

        // ---- O += P * V : 16 n8-tiles (headdim), accumulate over 4 k-chunks
#pragma unroll
        for (int jd = 0; jd < 16; jd++) {
            const __half* vr = &Vt[(jd * 8 + lr) * 72];
#pragma unroll
            for (int kt = 0; kt < 4; kt++) {
                unsigned bb[2];
                bb[0] = *(unsigned*)&vr[kt * 16 + 2 * mq];
                bb[1] = *(unsigned*)&vr[kt * 16 + 2 * mq + 8];
                mma16816(oc[jd], pa[kt], bb);
            }
        }
    }

    // ---- Epilogue: normalize, write half2 per tile per owned row ----
    float inv0 = 1.f / l0;
    float inv1 = 1.f / l1;
    size_t gr0 = base + (size_t)grow0 * ND;
    size_t gr1 = base + (size_t)grow1 * ND;
#pragma unroll
    for (int jd = 0; jd < 16; jd++) {
        int col = jd * 8 + 2 * mq;
        __half2 h0 = __floats2half2_rn(oc[jd][0] * inv0, oc[jd][1] * inv0);
        __half2 h1 = __floats2half2_rn(oc[jd][2] * inv1, oc[jd][3] * inv1);
        *(unsigned*)&g_attnh[gr0 + col] = *(unsigned*)&h0;
        *(unsigned*)&g_attnh[gr1 + col] = *(unsigned*)&h1;
    }
}

// ---------------------------------------------------------------------------
extern "C" void kernel_launch(void* const* d_in, const int* in_sizes, int n_in,
                              void* d_out, int out_size)
{
    (void)in_sizes; (void)n_in; (void)out_size;
    const float* x    = (const float*)d_in[0];
    const float* wq   = (const float*)d_in[1];
    const float* wk   = (const float*)d_in[2];
    const float* wv   = (const float*)d_in[3];
    const float* wo   = (const float*)d_in[4];
    const float* fcos = (const float*)d_in[5];
    const float* fsin = (const float*)d_in[6];
    // d_in[7] = mask: causal tril, implemented directly in attn_kernel
    float* out = (float*)d_out;

    const int GEMM_SMEM = 2 * 128 * 72 * 2 * 2;  // 73728 B
    cudaFuncSetAttribute(gemm_f16_kernel,
                         cudaFuncAttributeMaxDynamicSharedMemorySize, GEMM_SMEM);

    const int ATT_SMEM = (64 * 136 + 128 * 72) * 2;  // 35840 B
    cudaFuncSetAttribute(attn_kernel,
                         cudaFuncAttributeMaxDynamicSharedMemorySize, ATT_SMEM);

    // 0) fp32 -> fp16 pre-pass for x and all four weights
    f2h_kernel<<<dim3(4096, 1, 5), 256>>>(x, wq, wk, wv, wo);

    // 1) QKV projections (fused across grid.z), half in / fp32 out
    dim3 gqkv(32, 32, 3);
    gemm_f16_kernel<<<gqkv, 128, GEMM_SMEM>>>(nullptr, 0);

    // 2) RoPE on q and k (fp32 in-place)
    rope_kernel<<<65536, 256>>>(fcos, fsin);

    // 3) Causal flash attention (register-resident FA2, mma.sync)
    dim3 gatt(NS / 64, NH, NB);
    attn_kernel<<<gatt, 128, ATT_SMEM>>>();

    // 4) Output projection, half in / fp32 out
    dim3 go(32, 32, 1);
    gemm_f16_kernel<<<go, 128, GEMM_SMEM>>>(out, 1);
}